// round 1
// baseline (speedup 1.0000x reference)
#include <cuda_runtime.h>
#include <math.h>

#define CC    256
#define GG    4
#define NB    2
#define OMC   108          // G*K*3
#define MAXHW 4096
#define OCB   12           // out-channels per conv block
#define NOCB  9            // 108 / 12

// ---------------- scratch (static device globals; no runtime allocation) ----
__device__ float g_x1 [NB*CC*MAXHW];     // scaled input, channel-major [b][c][hw]
__device__ float g_xt [NB*MAXHW*CC];     // scaled input, pixel-major  [b][hw][c]
__device__ float g_om [NB*OMC*MAXHW];    // offset/mask conv output
__device__ float g_dcn[NB*MAXHW*CC];     // dcn gather output [b*hw][c]
__device__ float g_d  [NB*MAXHW*CC];     // proj output       [b*hw][c]
__device__ float g_x2t[NB*MAXHW*CC];     // after spatial gate [b*hw][c]
__device__ float g_pool [NB*CC];
__device__ float g_sfac [NB*CC];
__device__ float g_part [NB*16*CC];
__device__ float g_pool2[NB*CC];
__device__ float g_ab [4*NB*CC];         // a1,b1,a2,b2

// ---------------- stage A: channel scale attention --------------------------
__global__ __launch_bounds__(256) void k_pool(const float* __restrict__ x, int HW) {
    int c = blockIdx.x, b = blockIdx.y;
    const float* p = x + ((size_t)b*CC + c)*HW;
    float s = 0.f;
    for (int i = threadIdx.x; i < HW; i += 256) s += p[i];
    __shared__ float sm[8];
    int lane = threadIdx.x & 31, wid = threadIdx.x >> 5;
#pragma unroll
    for (int o = 16; o; o >>= 1) s += __shfl_down_sync(0xffffffffu, s, o);
    if (!lane) sm[wid] = s;
    __syncthreads();
    if (threadIdx.x == 0) {
        float t = 0.f;
#pragma unroll
        for (int i = 0; i < 8; i++) t += sm[i];
        g_pool[b*CC + c] = t / (float)HW;
    }
}

__global__ __launch_bounds__(256) void k_scale_gemv(const float* __restrict__ wsc,
                                                    const float* __restrict__ bsc) {
    int gw = (blockIdx.x*blockDim.x + threadIdx.x) >> 5;
    int lane = threadIdx.x & 31;
    if (gw >= NB*CC) return;
    int b = gw / CC, o = gw % CC;
    const float* wr = wsc + (size_t)o*CC;
    const float* pr = g_pool + b*CC;
    float s = 0.f;
#pragma unroll
    for (int i = 0; i < CC/32; i++) s = fmaf(wr[lane + i*32], pr[lane + i*32], s);
#pragma unroll
    for (int o2 = 16; o2; o2 >>= 1) s += __shfl_down_sync(0xffffffffu, s, o2);
    if (!lane) {
        s = (s + bsc[o] + 1.f) * 0.5f;
        g_sfac[b*CC + o] = fminf(fmaxf(s, 0.f), 1.f);
    }
}

__global__ __launch_bounds__(256) void k_apply(const float* __restrict__ x, int HW) {
    int hw = blockIdx.x*256 + threadIdx.x;
    int c  = blockIdx.y, b = blockIdx.z;
    float v = x[((size_t)b*CC + c)*HW + hw] * g_sfac[b*CC + c];
    g_x1[((size_t)b*CC + c)*HW + hw]   = v;
    g_xt[((size_t)b*HW + hw)*CC + c]   = v;
}

// ---------------- 3x3 conv producing offsets/masks --------------------------
// tile: 32 wide x 16 high, 256 threads, 2 pixels/thread, OCB out-channels/block
__global__ __launch_bounds__(256) void k_conv3x3(const float* __restrict__ wom,
                                                 const float* __restrict__ bom,
                                                 int H, int W) {
    int HW = H*W;
    int tx0 = blockIdx.x*32, ty0 = blockIdx.y*16;
    int zb = blockIdx.z;
    int b = zb / NOCB, oc0 = (zb % NOCB)*OCB;
    __shared__ float sIn[18*34];
    __shared__ float sW[OCB*9];
    int tid = threadIdx.x;
    int tx = tid & 31, ty = tid >> 5;          // ty in 0..7
    float a0[OCB], a1[OCB];
#pragma unroll
    for (int i = 0; i < OCB; i++) { a0[i] = 0.f; a1[i] = 0.f; }

    for (int c = 0; c < CC; c++) {
        __syncthreads();
        const float* xin = g_x1 + ((size_t)b*CC + c)*HW;
        for (int i = tid; i < 18*34; i += 256) {
            int r = i / 34, cl = i % 34;
            int gh = ty0 + r - 1, gw = tx0 + cl - 1;
            float v = 0.f;
            if ((unsigned)gh < (unsigned)H && (unsigned)gw < (unsigned)W)
                v = xin[gh*W + gw];
            sIn[i] = v;
        }
        if (tid < OCB*9)
            sW[tid] = wom[((size_t)(oc0 + tid/9)*CC + c)*9 + tid%9];
        __syncthreads();

        float r0[9], r1[9];
#pragma unroll
        for (int t = 0; t < 9; t++) {
            int dy = t/3, dx = t%3;
            r0[t] = sIn[(ty   + dy)*34 + tx + dx];
            r1[t] = sIn[(ty+8 + dy)*34 + tx + dx];
        }
#pragma unroll
        for (int oc = 0; oc < OCB; oc++) {
#pragma unroll
            for (int t = 0; t < 9; t++) {
                float w = sW[oc*9 + t];
                a0[oc] = fmaf(w, r0[t], a0[oc]);
                a1[oc] = fmaf(w, r1[t], a1[oc]);
            }
        }
    }
    int h0 = ty0 + ty, w0 = tx0 + tx;
#pragma unroll
    for (int oc = 0; oc < OCB; oc++) {
        float bia = bom[oc0 + oc];
        if (h0 < H && w0 < W)
            g_om[((size_t)b*OMC + oc0+oc)*HW + h0*W + w0] = a0[oc] + bia;
        if (h0+8 < H && w0 < W)
            g_om[((size_t)b*OMC + oc0+oc)*HW + (h0+8)*W + w0] = a1[oc] + bia;
    }
}

// ---------------- DCNv4 bilinear gather -------------------------------------
// one warp per (pixel, group); lanes cover channels lane & lane+32 of the group
__global__ __launch_bounds__(256) void k_dcn(int H, int W) {
    int HW = H*W;
    int warp = threadIdx.x >> 5, lane = threadIdx.x & 31;
    int hw = blockIdx.x*8 + warp;
    if (hw >= HW) return;
    int g = blockIdx.y, b = blockIdx.z;
    int h = hw / W, w = hw % W;
    const float* omb = g_om + (size_t)b*OMC*HW;
    const float* xb  = g_xt + (size_t)b*HW*CC + g*64;
    float acc0 = 0.f, acc1 = 0.f;
#pragma unroll
    for (int k = 0; k < 9; k++) {
        int ky = k/3 - 1, kx = k%3 - 1;
        int ch = (g*9 + k)*3;
        float offy = omb[(size_t)(ch+0)*HW + hw];
        float offx = omb[(size_t)(ch+1)*HW + hw];
        float msk  = omb[(size_t)(ch+2)*HW + hw];
        float py = (float)(h + ky) + offy;
        float px = (float)(w + kx) + offx;
        float y0f = floorf(py), x0f = floorf(px);
        float fy = py - y0f, fx = px - x0f;
        int y0 = (int)y0f, x0 = (int)x0f;
#pragma unroll
        for (int t = 0; t < 4; t++) {
            int dy = t >> 1, dx = t & 1;
            int yy = y0 + dy, xx = x0 + dx;
            float wgt = (dy ? fy : 1.f - fy) * (dx ? fx : 1.f - fx);
            bool valid = (yy >= 0) && (yy < H) && (xx >= 0) && (xx < W);
            float weff = valid ? wgt * msk : 0.f;
            if (weff != 0.f) {                 // warp-uniform branch
                int yc = min(max(yy, 0), H-1);
                int xc = min(max(xx, 0), W-1);
                const float* p = xb + (size_t)(yc*W + xc)*CC;
                acc0 = fmaf(weff, p[lane],      acc0);
                acc1 = fmaf(weff, p[lane + 32], acc1);
            }
        }
    }
    size_t o = ((size_t)b*HW + hw)*CC + g*64;
    g_dcn[o + lane]      = acc0;
    g_dcn[o + lane + 32] = acc1;
}

// ---------------- 1x1 projection GEMM: D[m][n] = dcn[m][k] * wp[n][k] + bp[n]
__global__ __launch_bounds__(256) void k_proj(const float* __restrict__ wp,
                                              const float* __restrict__ bp, int M) {
    __shared__ float As[16][64];
    __shared__ float Bs[16][64];
    int tid = threadIdx.x;
    int m0 = blockIdx.x*64, n0 = blockIdx.y*64;
    int tm = tid >> 4, tn = tid & 15;
    float acc[4][4];
#pragma unroll
    for (int i = 0; i < 4; i++)
#pragma unroll
        for (int j = 0; j < 4; j++) acc[i][j] = 0.f;
    int row = tid >> 2, kq = (tid & 3) << 2;
    for (int k0 = 0; k0 < CC; k0 += 16) {
        float4 av = *(const float4*)(g_dcn + (size_t)(m0+row)*CC + k0 + kq);
        float4 bv = *(const float4*)(wp    + (size_t)(n0+row)*CC + k0 + kq);
        As[kq+0][row]=av.x; As[kq+1][row]=av.y; As[kq+2][row]=av.z; As[kq+3][row]=av.w;
        Bs[kq+0][row]=bv.x; Bs[kq+1][row]=bv.y; Bs[kq+2][row]=bv.z; Bs[kq+3][row]=bv.w;
        __syncthreads();
#pragma unroll
        for (int kk = 0; kk < 16; kk++) {
            float ra[4], rb[4];
#pragma unroll
            for (int i = 0; i < 4; i++) { ra[i] = As[kk][tm*4+i]; rb[i] = Bs[kk][tn*4+i]; }
#pragma unroll
            for (int i = 0; i < 4; i++)
#pragma unroll
                for (int j = 0; j < 4; j++) acc[i][j] = fmaf(ra[i], rb[j], acc[i][j]);
        }
        __syncthreads();
    }
#pragma unroll
    for (int i = 0; i < 4; i++)
#pragma unroll
        for (int j = 0; j < 4; j++)
            g_d[(size_t)(m0 + tm*4 + i)*CC + n0 + tn*4 + j] = acc[i][j] + bp[n0 + tn*4 + j];
}

// ---------------- channel LayerNorm + sigmoid gate --------------------------
__global__ __launch_bounds__(256) void k_lngate(const float* __restrict__ lng,
                                                const float* __restrict__ lnb, int HW) {
    int r = blockIdx.x;            // 0..B*HW-1
    int c = threadIdx.x;
    size_t base = (size_t)r*CC;
    float v = g_d[base + c];
    float s1 = v, s2 = v*v;
    __shared__ float sm1[8], sm2[8];
    __shared__ float stat[2];
    int lane = c & 31, wid = c >> 5;
#pragma unroll
    for (int o = 16; o; o >>= 1) {
        s1 += __shfl_down_sync(0xffffffffu, s1, o);
        s2 += __shfl_down_sync(0xffffffffu, s2, o);
    }
    if (!lane) { sm1[wid] = s1; sm2[wid] = s2; }
    __syncthreads();
    if (c == 0) {
        float a = 0.f, q = 0.f;
#pragma unroll
        for (int i = 0; i < 8; i++) { a += sm1[i]; q += sm2[i]; }
        float mu = a * (1.f/CC);
        stat[0] = mu;
        stat[1] = q * (1.f/CC) - mu*mu;
    }
    __syncthreads();
    float mu = stat[0], var = stat[1];
    float dn = (v - mu) * rsqrtf(var + 1e-5f) * lng[c] + lnb[c];
    float gate = 1.f / (1.f + expf(-dn));
    g_x2t[base + c] = g_xt[base + c] * gate;
}

// ---------------- task attention --------------------------------------------
__global__ __launch_bounds__(256) void k_pool2a(int HW, int nSlab) {
    int b = blockIdx.y, slab = blockIdx.x;
    int c = threadIdx.x;
    int rows = HW / nSlab;
    int r0 = slab * rows;
    float s = 0.f;
    for (int r = r0; r < r0 + rows; r++)
        s += g_x2t[((size_t)b*HW + r)*CC + c];
    g_part[(b*16 + slab)*CC + c] = s;
}

__global__ __launch_bounds__(256) void k_pool2b(int HW, int nSlab) {
    int b = blockIdx.x, c = threadIdx.x;
    float s = 0.f;
    for (int i = 0; i < nSlab; i++) s += g_part[(b*16 + i)*CC + c];
    g_pool2[b*CC + c] = s / (float)HW;
}

__global__ __launch_bounds__(256) void k_task_gemv(
        const float* __restrict__ wa1, const float* __restrict__ ba1,
        const float* __restrict__ wb1, const float* __restrict__ bb1,
        const float* __restrict__ wa2, const float* __restrict__ ba2,
        const float* __restrict__ wb2, const float* __restrict__ bb2) {
    int gw = (blockIdx.x*blockDim.x + threadIdx.x) >> 5;
    int lane = threadIdx.x & 31;
    if (gw >= 4*NB*CC) return;
    int which = gw / (NB*CC);
    int rem = gw % (NB*CC);
    int b = rem / CC, o = rem % CC;
    const float* ws = (which == 0) ? wa1 : (which == 1) ? wb1 : (which == 2) ? wa2 : wb2;
    const float* bs = (which == 0) ? ba1 : (which == 1) ? bb1 : (which == 2) ? ba2 : bb2;
    const float* wr = ws + (size_t)o*CC;
    const float* pr = g_pool2 + b*CC;
    float s = 0.f;
#pragma unroll
    for (int i = 0; i < CC/32; i++) s = fmaf(wr[lane + i*32], pr[lane + i*32], s);
#pragma unroll
    for (int o2 = 16; o2; o2 >>= 1) s += __shfl_down_sync(0xffffffffu, s, o2);
    if (!lane) g_ab[which*NB*CC + b*CC + o] = fmaxf(s + bs[o], 0.f);
}

// gated output + transpose back to [b][c][hw]
__global__ __launch_bounds__(256) void k_taskout(float* __restrict__ out, int HW) {
    __shared__ float t[32][33];
    int b = blockIdx.z;
    int hw0 = blockIdx.x*32, c0 = blockIdx.y*32;
    int tx = threadIdx.x, ty = threadIdx.y;   // 32 x 8
#pragma unroll
    for (int i = 0; i < 4; i++) {
        int hw = hw0 + ty + i*8, c = c0 + tx;
        float v  = g_x2t[((size_t)b*HW + hw)*CC + c];
        float A1 = g_ab[0*NB*CC + b*CC + c];
        float B1 = g_ab[1*NB*CC + b*CC + c];
        float A2 = g_ab[2*NB*CC + b*CC + c];
        float B2 = g_ab[3*NB*CC + b*CC + c];
        t[tx][ty + i*8] = fmaxf(fmaf(A1, v, B1), fmaf(A2, v, B2));
    }
    __syncthreads();
#pragma unroll
    for (int i = 0; i < 4; i++) {
        int c = c0 + ty + i*8, hw = hw0 + tx;
        out[((size_t)b*CC + c)*HW + hw] = t[ty + i*8][tx];
    }
}

// ---------------- launch ------------------------------------------------------
extern "C" void kernel_launch(void* const* d_in, const int* in_sizes, int n_in,
                              void* d_out, int out_size) {
    const float* f[3] = { (const float*)d_in[0], (const float*)d_in[1], (const float*)d_in[2] };
    const float* w_scale = (const float*)d_in[3];
    const float* b_scale = (const float*)d_in[4];
    const float* w_om    = (const float*)d_in[5];
    const float* b_om    = (const float*)d_in[6];
    const float* w_proj  = (const float*)d_in[7];
    const float* b_proj  = (const float*)d_in[8];
    const float* ln_g    = (const float*)d_in[9];
    const float* ln_b    = (const float*)d_in[10];
    const float* wa1 = (const float*)d_in[11];
    const float* ba1 = (const float*)d_in[12];
    const float* wb1 = (const float*)d_in[13];
    const float* bb1 = (const float*)d_in[14];
    const float* wa2 = (const float*)d_in[15];
    const float* ba2 = (const float*)d_in[16];
    const float* wb2 = (const float*)d_in[17];
    const float* bb2 = (const float*)d_in[18];
    float* out = (float*)d_out;

    const int Hs[3] = {64, 32, 16};
    size_t ooff = 0;
    for (int s = 0; s < 3; s++) {
        int H = Hs[s], W = Hs[s], HW = H*W;
        int M = NB*HW;
        int nSlab = HW >= 4096 ? 16 : (HW >= 1024 ? 4 : 1);

        k_pool<<<dim3(CC, NB), 256>>>(f[s], HW);
        k_scale_gemv<<<(NB*CC*32 + 255)/256, 256>>>(w_scale, b_scale);
        k_apply<<<dim3(HW/256, CC, NB), 256>>>(f[s], HW);
        k_conv3x3<<<dim3((W+31)/32, (H+15)/16, NB*NOCB), 256>>>(w_om, b_om, H, W);
        k_dcn<<<dim3(HW/8, GG, NB), 256>>>(H, W);
        k_proj<<<dim3(M/64, CC/64), 256>>>(w_proj, b_proj, M);
        k_lngate<<<M, 256>>>(ln_g, ln_b, HW);
        k_pool2a<<<dim3(nSlab, NB), 256>>>(HW, nSlab);
        k_pool2b<<<NB, 256>>>(HW, nSlab);
        k_task_gemv<<<(4*NB*CC*32 + 255)/256, 256>>>(wa1, ba1, wb1, bb1, wa2, ba2, wb2, bb2);
        k_taskout<<<dim3(HW/32, CC/32, NB), dim3(32, 8)>>>(out + ooff, HW);

        ooff += (size_t)NB*CC*HW;
    }
}

// round 2
// speedup vs baseline: 2.8254x; 2.8254x over previous
#include <cuda_runtime.h>
#include <math.h>

#define CC    256
#define GG    4
#define NB    2
#define OMC   108          // G*K*3
#define MAXHW 4096
#define OCB   12           // out-channels per conv block
#define NOCB  9            // 108 / 12
#define CB    4            // channels per conv inner batch
#define CSMAX 8

// ---------------- scratch (static device globals; no runtime allocation) ----
__device__ float g_x1 [NB*CC*MAXHW];     // scaled input, channel-major [b][c][hw]
__device__ float g_xt [NB*MAXHW*CC];     // scaled input, pixel-major  [b][hw][c]
__device__ float g_om [NB*OMC*MAXHW];    // offset/mask conv output
__device__ float g_omp[CSMAX*NB*OMC*MAXHW]; // conv partials (channel split)
__device__ float g_dcn[NB*MAXHW*CC];     // dcn gather output [b*hw][c]
__device__ float g_d  [NB*MAXHW*CC];     // proj output       [b*hw][c]
__device__ float g_x2t[NB*MAXHW*CC];     // after spatial gate [b*hw][c]
__device__ float g_pool [NB*CC];
__device__ float g_sfac [NB*CC];
__device__ float g_part [NB*16*CC];
__device__ float g_pool2[NB*CC];
__device__ float g_ab [4*NB*CC];         // a1,b1,a2,b2

// ---------------- stage A: channel scale attention --------------------------
__global__ __launch_bounds__(256) void k_pool(const float* __restrict__ x, int HW) {
    int c = blockIdx.x, b = blockIdx.y;
    const float* p = x + ((size_t)b*CC + c)*HW;
    float s = 0.f;
    for (int i = threadIdx.x; i < HW; i += 256) s += p[i];
    __shared__ float sm[8];
    int lane = threadIdx.x & 31, wid = threadIdx.x >> 5;
#pragma unroll
    for (int o = 16; o; o >>= 1) s += __shfl_down_sync(0xffffffffu, s, o);
    if (!lane) sm[wid] = s;
    __syncthreads();
    if (threadIdx.x == 0) {
        float t = 0.f;
#pragma unroll
        for (int i = 0; i < 8; i++) t += sm[i];
        g_pool[b*CC + c] = t / (float)HW;
    }
}

__global__ __launch_bounds__(256) void k_scale_gemv(const float* __restrict__ wsc,
                                                    const float* __restrict__ bsc) {
    int gw = (blockIdx.x*blockDim.x + threadIdx.x) >> 5;
    int lane = threadIdx.x & 31;
    if (gw >= NB*CC) return;
    int b = gw / CC, o = gw % CC;
    const float* wr = wsc + (size_t)o*CC;
    const float* pr = g_pool + b*CC;
    float s = 0.f;
#pragma unroll
    for (int i = 0; i < CC/32; i++) s = fmaf(wr[lane + i*32], pr[lane + i*32], s);
#pragma unroll
    for (int o2 = 16; o2; o2 >>= 1) s += __shfl_down_sync(0xffffffffu, s, o2);
    if (!lane) {
        s = (s + bsc[o] + 1.f) * 0.5f;
        g_sfac[b*CC + o] = fminf(fmaxf(s, 0.f), 1.f);
    }
}

__global__ __launch_bounds__(256) void k_apply(const float* __restrict__ x, int HW) {
    int hw = blockIdx.x*256 + threadIdx.x;
    int c  = blockIdx.y, b = blockIdx.z;
    float v = x[((size_t)b*CC + c)*HW + hw] * g_sfac[b*CC + c];
    g_x1[((size_t)b*CC + c)*HW + hw]   = v;
    g_xt[((size_t)b*HW + hw)*CC + c]   = v;
}

// ---------------- 3x3 conv producing offsets/masks --------------------------
// tile: 32 wide x 16 high, 256 threads, 2 pixels/thread, OCB out-channels,
// CB=4 channels per inner batch (float4 from pixel-major g_xt),
// CS-way channel split across blocks -> partials in g_omp.
__global__ __launch_bounds__(256,2) void k_conv3x3(const float* __restrict__ wom,
                                                   int H, int W, int CS) {
    int HW = H*W;
    int tx0 = blockIdx.x*32, ty0 = blockIdx.y*16;
    int zb = blockIdx.z;
    int cs = zb % CS;
    int rest = zb / CS;
    int b = rest / NOCB, oc0 = (rest % NOCB)*OCB;
    int cbase = cs * (CC/CS), cend = cbase + CC/CS;

    __shared__ float sIn[CB][18*35];
    __shared__ float sW[OCB][CB*9];

    int tid = threadIdx.x;
    int tx = tid & 31, ty = tid >> 5;          // ty in 0..7
    float a0[OCB], a1[OCB];
#pragma unroll
    for (int i = 0; i < OCB; i++) { a0[i] = 0.f; a1[i] = 0.f; }

    const float* xb = g_xt + (size_t)b*HW*CC;

    for (int c0 = cbase; c0 < cend; c0 += CB) {
        __syncthreads();
        // fill input smem: 18x34 halo, 4 channels at once via float4
        for (int i = tid; i < 18*34; i += 256) {
            int r = i / 34, cl = i - r*34;
            int gh = ty0 + r - 1, gw = tx0 + cl - 1;
            float4 v = make_float4(0.f, 0.f, 0.f, 0.f);
            if ((unsigned)gh < (unsigned)H && (unsigned)gw < (unsigned)W)
                v = *(const float4*)(xb + (size_t)(gh*W + gw)*CC + c0);
            int o = r*35 + cl;
            sIn[0][o] = v.x; sIn[1][o] = v.y; sIn[2][o] = v.z; sIn[3][o] = v.w;
        }
        // weights: OCB x CB x 9
        for (int i = tid; i < OCB*CB*9; i += 256) {
            int oc = i / (CB*9);
            int rem = i - oc*(CB*9);
            int ch = rem / 9, t = rem - ch*9;
            sW[oc][ch*9 + t] = wom[((size_t)(oc0 + oc)*CC + c0 + ch)*9 + t];
        }
        __syncthreads();

#pragma unroll
        for (int ch = 0; ch < CB; ch++) {
            float r0[9], r1[9];
#pragma unroll
            for (int t = 0; t < 9; t++) {
                int dy = t/3, dx = t%3;
                r0[t] = sIn[ch][(ty   + dy)*35 + tx + dx];
                r1[t] = sIn[ch][(ty+8 + dy)*35 + tx + dx];
            }
#pragma unroll
            for (int oc = 0; oc < OCB; oc++) {
#pragma unroll
                for (int t = 0; t < 9; t++) {
                    float w = sW[oc][ch*9 + t];
                    a0[oc] = fmaf(w, r0[t], a0[oc]);
                    a1[oc] = fmaf(w, r1[t], a1[oc]);
                }
            }
        }
    }
    int h0 = ty0 + ty, w0 = tx0 + tx;
    size_t pbase = ((size_t)cs*NB + b)*OMC*HW;
#pragma unroll
    for (int oc = 0; oc < OCB; oc++) {
        size_t o = pbase + (size_t)(oc0+oc)*HW;
        if (h0 < H && w0 < W)
            g_omp[o + h0*W + w0] = a0[oc];
        if (h0+8 < H && w0 < W)
            g_omp[o + (h0+8)*W + w0] = a1[oc];
    }
}

// reduce channel-split partials + bias
__global__ __launch_bounds__(256) void k_omred(const float* __restrict__ bom,
                                               int HW, int CS) {
    int idx = blockIdx.x*256 + threadIdx.x;
    int tot = NB*OMC*HW;
    if (idx >= tot) return;
    int oc = (idx / HW) % OMC;
    int b  = idx / (OMC*HW);
    int rem = idx - b*OMC*HW;          // oc*HW + hw within batch b
    float s = bom[oc];
    for (int cs = 0; cs < CS; cs++)
        s += g_omp[((size_t)cs*NB + b)*OMC*HW + rem];
    g_om[idx] = s;
}

// ---------------- DCNv4 bilinear gather -------------------------------------
// one warp per (pixel, group); lanes cover channels lane & lane+32 of the group
__global__ __launch_bounds__(256) void k_dcn(int H, int W) {
    int HW = H*W;
    int warp = threadIdx.x >> 5, lane = threadIdx.x & 31;
    int hw = blockIdx.x*8 + warp;
    if (hw >= HW) return;
    int g = blockIdx.y, b = blockIdx.z;
    int h = hw / W, w = hw % W;
    const float* omb = g_om + (size_t)b*OMC*HW;
    const float* xb  = g_xt + (size_t)b*HW*CC + g*64;
    float acc0 = 0.f, acc1 = 0.f;
#pragma unroll
    for (int k = 0; k < 9; k++) {
        int ky = k/3 - 1, kx = k%3 - 1;
        int ch = (g*9 + k)*3;
        float offy = omb[(size_t)(ch+0)*HW + hw];
        float offx = omb[(size_t)(ch+1)*HW + hw];
        float msk  = omb[(size_t)(ch+2)*HW + hw];
        float py = (float)(h + ky) + offy;
        float px = (float)(w + kx) + offx;
        float y0f = floorf(py), x0f = floorf(px);
        float fy = py - y0f, fx = px - x0f;
        int y0 = (int)y0f, x0 = (int)x0f;
#pragma unroll
        for (int t = 0; t < 4; t++) {
            int dy = t >> 1, dx = t & 1;
            int yy = y0 + dy, xx = x0 + dx;
            float wgt = (dy ? fy : 1.f - fy) * (dx ? fx : 1.f - fx);
            bool valid = (yy >= 0) && (yy < H) && (xx >= 0) && (xx < W);
            float weff = valid ? wgt * msk : 0.f;
            if (weff != 0.f) {                 // warp-uniform branch
                int yc = min(max(yy, 0), H-1);
                int xc = min(max(xx, 0), W-1);
                const float* p = xb + (size_t)(yc*W + xc)*CC;
                acc0 = fmaf(weff, p[lane],      acc0);
                acc1 = fmaf(weff, p[lane + 32], acc1);
            }
        }
    }
    size_t o = ((size_t)b*HW + hw)*CC + g*64;
    g_dcn[o + lane]      = acc0;
    g_dcn[o + lane + 32] = acc1;
}

// ---------------- 1x1 projection GEMM: D[m][n] = dcn[m][k] * wp[n][k] + bp[n]
__global__ __launch_bounds__(256) void k_proj(const float* __restrict__ wp,
                                              const float* __restrict__ bp, int M) {
    __shared__ float As[16][64];
    __shared__ float Bs[16][64];
    int tid = threadIdx.x;
    int m0 = blockIdx.x*64, n0 = blockIdx.y*64;
    int tm = tid >> 4, tn = tid & 15;
    float acc[4][4];
#pragma unroll
    for (int i = 0; i < 4; i++)
#pragma unroll
        for (int j = 0; j < 4; j++) acc[i][j] = 0.f;
    int row = tid >> 2, kq = (tid & 3) << 2;
    for (int k0 = 0; k0 < CC; k0 += 16) {
        float4 av = *(const float4*)(g_dcn + (size_t)(m0+row)*CC + k0 + kq);
        float4 bv = *(const float4*)(wp    + (size_t)(n0+row)*CC + k0 + kq);
        As[kq+0][row]=av.x; As[kq+1][row]=av.y; As[kq+2][row]=av.z; As[kq+3][row]=av.w;
        Bs[kq+0][row]=bv.x; Bs[kq+1][row]=bv.y; Bs[kq+2][row]=bv.z; Bs[kq+3][row]=bv.w;
        __syncthreads();
#pragma unroll
        for (int kk = 0; kk < 16; kk++) {
            float ra[4], rb[4];
#pragma unroll
            for (int i = 0; i < 4; i++) { ra[i] = As[kk][tm*4+i]; rb[i] = Bs[kk][tn*4+i]; }
#pragma unroll
            for (int i = 0; i < 4; i++)
#pragma unroll
                for (int j = 0; j < 4; j++) acc[i][j] = fmaf(ra[i], rb[j], acc[i][j]);
        }
        __syncthreads();
    }
#pragma unroll
    for (int i = 0; i < 4; i++)
#pragma unroll
        for (int j = 0; j < 4; j++)
            g_d[(size_t)(m0 + tm*4 + i)*CC + n0 + tn*4 + j] = acc[i][j] + bp[n0 + tn*4 + j];
}

// ---------------- channel LayerNorm + sigmoid gate --------------------------
__global__ __launch_bounds__(256) void k_lngate(const float* __restrict__ lng,
                                                const float* __restrict__ lnb, int HW) {
    int r = blockIdx.x;            // 0..B*HW-1
    int c = threadIdx.x;
    size_t base = (size_t)r*CC;
    float v = g_d[base + c];
    float s1 = v, s2 = v*v;
    __shared__ float sm1[8], sm2[8];
    __shared__ float stat[2];
    int lane = c & 31, wid = c >> 5;
#pragma unroll
    for (int o = 16; o; o >>= 1) {
        s1 += __shfl_down_sync(0xffffffffu, s1, o);
        s2 += __shfl_down_sync(0xffffffffu, s2, o);
    }
    if (!lane) { sm1[wid] = s1; sm2[wid] = s2; }
    __syncthreads();
    if (c == 0) {
        float a = 0.f, q = 0.f;
#pragma unroll
        for (int i = 0; i < 8; i++) { a += sm1[i]; q += sm2[i]; }
        float mu = a * (1.f/CC);
        stat[0] = mu;
        stat[1] = q * (1.f/CC) - mu*mu;
    }
    __syncthreads();
    float mu = stat[0], var = stat[1];
    float dn = (v - mu) * rsqrtf(var + 1e-5f) * lng[c] + lnb[c];
    float gate = 1.f / (1.f + expf(-dn));
    g_x2t[base + c] = g_xt[base + c] * gate;
}

// ---------------- task attention --------------------------------------------
__global__ __launch_bounds__(256) void k_pool2a(int HW, int nSlab) {
    int b = blockIdx.y, slab = blockIdx.x;
    int c = threadIdx.x;
    int rows = HW / nSlab;
    int r0 = slab * rows;
    float s = 0.f;
    for (int r = r0; r < r0 + rows; r++)
        s += g_x2t[((size_t)b*HW + r)*CC + c];
    g_part[(b*16 + slab)*CC + c] = s;
}

__global__ __launch_bounds__(256) void k_pool2b(int HW, int nSlab) {
    int b = blockIdx.x, c = threadIdx.x;
    float s = 0.f;
    for (int i = 0; i < nSlab; i++) s += g_part[(b*16 + i)*CC + c];
    g_pool2[b*CC + c] = s / (float)HW;
}

__global__ __launch_bounds__(256) void k_task_gemv(
        const float* __restrict__ wa1, const float* __restrict__ ba1,
        const float* __restrict__ wb1, const float* __restrict__ bb1,
        const float* __restrict__ wa2, const float* __restrict__ ba2,
        const float* __restrict__ wb2, const float* __restrict__ bb2) {
    int gw = (blockIdx.x*blockDim.x + threadIdx.x) >> 5;
    int lane = threadIdx.x & 31;
    if (gw >= 4*NB*CC) return;
    int which = gw / (NB*CC);
    int rem = gw % (NB*CC);
    int b = rem / CC, o = rem % CC;
    const float* ws = (which == 0) ? wa1 : (which == 1) ? wb1 : (which == 2) ? wa2 : wb2;
    const float* bs = (which == 0) ? ba1 : (which == 1) ? bb1 : (which == 2) ? ba2 : bb2;
    const float* wr = ws + (size_t)o*CC;
    const float* pr = g_pool2 + b*CC;
    float s = 0.f;
#pragma unroll
    for (int i = 0; i < CC/32; i++) s = fmaf(wr[lane + i*32], pr[lane + i*32], s);
#pragma unroll
    for (int o2 = 16; o2; o2 >>= 1) s += __shfl_down_sync(0xffffffffu, s, o2);
    if (!lane) g_ab[which*NB*CC + b*CC + o] = fmaxf(s + bs[o], 0.f);
}

// gated output + transpose back to [b][c][hw]
__global__ __launch_bounds__(256) void k_taskout(float* __restrict__ out, int HW) {
    __shared__ float t[32][33];
    int b = blockIdx.z;
    int hw0 = blockIdx.x*32, c0 = blockIdx.y*32;
    int tx = threadIdx.x, ty = threadIdx.y;   // 32 x 8
#pragma unroll
    for (int i = 0; i < 4; i++) {
        int hw = hw0 + ty + i*8, c = c0 + tx;
        float v  = g_x2t[((size_t)b*HW + hw)*CC + c];
        float A1 = g_ab[0*NB*CC + b*CC + c];
        float B1 = g_ab[1*NB*CC + b*CC + c];
        float A2 = g_ab[2*NB*CC + b*CC + c];
        float B2 = g_ab[3*NB*CC + b*CC + c];
        t[tx][ty + i*8] = fmaxf(fmaf(A1, v, B1), fmaf(A2, v, B2));
    }
    __syncthreads();
#pragma unroll
    for (int i = 0; i < 4; i++) {
        int c = c0 + ty + i*8, hw = hw0 + tx;
        out[((size_t)b*CC + c)*HW + hw] = t[ty + i*8][tx];
    }
}

// ---------------- launch ------------------------------------------------------
extern "C" void kernel_launch(void* const* d_in, const int* in_sizes, int n_in,
                              void* d_out, int out_size) {
    const float* f[3] = { (const float*)d_in[0], (const float*)d_in[1], (const float*)d_in[2] };
    const float* w_scale = (const float*)d_in[3];
    const float* b_scale = (const float*)d_in[4];
    const float* w_om    = (const float*)d_in[5];
    const float* b_om    = (const float*)d_in[6];
    const float* w_proj  = (const float*)d_in[7];
    const float* b_proj  = (const float*)d_in[8];
    const float* ln_g    = (const float*)d_in[9];
    const float* ln_b    = (const float*)d_in[10];
    const float* wa1 = (const float*)d_in[11];
    const float* ba1 = (const float*)d_in[12];
    const float* wb1 = (const float*)d_in[13];
    const float* bb1 = (const float*)d_in[14];
    const float* wa2 = (const float*)d_in[15];
    const float* ba2 = (const float*)d_in[16];
    const float* wb2 = (const float*)d_in[17];
    const float* bb2 = (const float*)d_in[18];
    float* out = (float*)d_out;

    const int Hs[3] = {64, 32, 16};
    const int CSs[3] = {2, 4, 8};
    size_t ooff = 0;
    for (int s = 0; s < 3; s++) {
        int H = Hs[s], W = Hs[s], HW = H*W;
        int M = NB*HW;
        int CS = CSs[s];
        int nSlab = HW >= 4096 ? 16 : (HW >= 1024 ? 4 : 1);

        k_pool<<<dim3(CC, NB), 256>>>(f[s], HW);
        k_scale_gemv<<<(NB*CC*32 + 255)/256, 256>>>(w_scale, b_scale);
        k_apply<<<dim3(HW/256, CC, NB), 256>>>(f[s], HW);
        k_conv3x3<<<dim3((W+31)/32, (H+15)/16, NB*NOCB*CS), 256>>>(w_om, H, W, CS);
        k_omred<<<(NB*OMC*HW + 255)/256, 256>>>(b_om, HW, CS);
        k_dcn<<<dim3(HW/8, GG, NB), 256>>>(H, W);
        k_proj<<<dim3(M/64, CC/64), 256>>>(w_proj, b_proj, M);
        k_lngate<<<M, 256>>>(ln_g, ln_b, HW);
        k_pool2a<<<dim3(nSlab, NB), 256>>>(HW, nSlab);
        k_pool2b<<<NB, 256>>>(HW, nSlab);
        k_task_gemv<<<(4*NB*CC*32 + 255)/256, 256>>>(wa1, ba1, wb1, bb1, wa2, ba2, wb2, bb2);
        k_taskout<<<dim3(HW/32, CC/32, NB), dim3(32, 8)>>>(out + ooff, HW);

        ooff += (size_t)NB*CC*HW;
    }
}

// round 3
// speedup vs baseline: 2.8743x; 1.0173x over previous
#include <cuda_runtime.h>
#include <math.h>

#define CC    256
#define GG    4
#define NB    2
#define OMC   108          // G*K*3
#define MAXHW 4096
#define OCB   12           // out-channels per conv block
#define NOCB  9            // 108 / 12
#define CB    4            // channels per conv inner batch
#define CSMAX 16

typedef unsigned long long ull;

__device__ __forceinline__ ull f2pk(float lo, float hi) {
    ull r; asm("mov.b64 %0, {%1, %2};" : "=l"(r) : "f"(lo), "f"(hi)); return r;
}
__device__ __forceinline__ void f2fma(ull &d, ull a, ull b) {
    asm("fma.rn.f32x2 %0, %1, %2, %0;" : "+l"(d) : "l"(a), "l"(b));
}
__device__ __forceinline__ float2 f2up(ull v) {
    float2 o; asm("mov.b64 {%0, %1}, %2;" : "=f"(o.x), "=f"(o.y) : "l"(v)); return o;
}

// ---------------- scratch (static device globals; no runtime allocation) ----
__device__ float g_xt [NB*MAXHW*CC];     // scaled input, pixel-major  [b][hw][c]
__device__ float g_om [NB*OMC*MAXHW];    // offset/mask conv output
__device__ float g_omp[CSMAX*NB*OMC*MAXHW]; // conv partials (channel split)
__device__ float g_dcn[NB*MAXHW*CC];     // dcn gather output [b*hw][c]
__device__ float g_d  [NB*MAXHW*CC];     // proj output       [b*hw][c]
__device__ float g_x2t[NB*MAXHW*CC];     // after spatial gate [b*hw][c]
__device__ ull   g_w2 [OMC*CC*9];        // conv weights splatted {w,w}
__device__ float g_pool [NB*CC];
__device__ float g_sfac [NB*CC];
__device__ float g_part [NB*16*CC];
__device__ float g_pool2[NB*CC];
__device__ float g_ab [4*NB*CC];         // a1,b1,a2,b2

// ---------------- weight splat prep ------------------------------------------
__global__ __launch_bounds__(256) void k_wprep(const float* __restrict__ wom) {
    int i = blockIdx.x*256 + threadIdx.x;
    if (i < OMC*CC*9) { float w = wom[i]; g_w2[i] = f2pk(w, w); }
}

// ---------------- stage A: channel scale attention --------------------------
__global__ __launch_bounds__(256) void k_pool(const float* __restrict__ x, int HW) {
    int c = blockIdx.x, b = blockIdx.y;
    const float* p = x + ((size_t)b*CC + c)*HW;
    float s = 0.f;
    for (int i = threadIdx.x; i < HW; i += 256) s += p[i];
    __shared__ float sm[8];
    int lane = threadIdx.x & 31, wid = threadIdx.x >> 5;
#pragma unroll
    for (int o = 16; o; o >>= 1) s += __shfl_down_sync(0xffffffffu, s, o);
    if (!lane) sm[wid] = s;
    __syncthreads();
    if (threadIdx.x == 0) {
        float t = 0.f;
#pragma unroll
        for (int i = 0; i < 8; i++) t += sm[i];
        g_pool[b*CC + c] = t / (float)HW;
    }
}

__global__ __launch_bounds__(256) void k_scale_gemv(const float* __restrict__ wsc,
                                                    const float* __restrict__ bsc) {
    int gw = (blockIdx.x*blockDim.x + threadIdx.x) >> 5;
    int lane = threadIdx.x & 31;
    if (gw >= NB*CC) return;
    int b = gw / CC, o = gw % CC;
    const float* wr = wsc + (size_t)o*CC;
    const float* pr = g_pool + b*CC;
    float s = 0.f;
#pragma unroll
    for (int i = 0; i < CC/32; i++) s = fmaf(wr[lane + i*32], pr[lane + i*32], s);
#pragma unroll
    for (int o2 = 16; o2; o2 >>= 1) s += __shfl_down_sync(0xffffffffu, s, o2);
    if (!lane) {
        s = (s + bsc[o] + 1.f) * 0.5f;
        g_sfac[b*CC + o] = fminf(fmaxf(s, 0.f), 1.f);
    }
}

__global__ __launch_bounds__(256) void k_apply(const float* __restrict__ x, int HW) {
    int hw = blockIdx.x*256 + threadIdx.x;
    int c  = blockIdx.y, b = blockIdx.z;
    float v = x[((size_t)b*CC + c)*HW + hw] * g_sfac[b*CC + c];
    g_xt[((size_t)b*HW + hw)*CC + c] = v;
}

// ---------------- 3x3 conv producing offsets/masks --------------------------
// tile 32x32, 256 threads, 4 pixels/thread as 2 f32x2 pairs,
// OCB out-channels, CB channels per inner batch, CS-way channel split.
__global__ __launch_bounds__(256,2) void k_conv3x3(int H, int W, int CS) {
    int HW = H*W;
    int tx0 = blockIdx.x*32, ty0 = blockIdx.y*32;
    int zb = blockIdx.z;
    int cs = zb % CS;
    int rest = zb / CS;
    int b = rest / NOCB, oc0 = (rest % NOCB)*OCB;
    int cbase = cs * (CC/CS), cend = cbase + CC/CS;

    __shared__ float sIn[CB][34*35];
    __shared__ ull sW2[OCB*CB*9];

    int tid = threadIdx.x;
    int tx = tid & 31, ty = tid >> 5;          // ty in 0..7
    ull accA[OCB], accB[OCB];
#pragma unroll
    for (int i = 0; i < OCB; i++) { accA[i] = 0ull; accB[i] = 0ull; }

    const float* xb = g_xt + (size_t)b*HW*CC;

    for (int c0 = cbase; c0 < cend; c0 += CB) {
        __syncthreads();
        // fill halo 34x34, 4 channels at once via float4 from pixel-major g_xt
        for (int i = tid; i < 34*34; i += 256) {
            int r = i / 34, cl = i - r*34;
            int gh = ty0 + r - 1, gw = tx0 + cl - 1;
            float4 v = make_float4(0.f, 0.f, 0.f, 0.f);
            if ((unsigned)gh < (unsigned)H && (unsigned)gw < (unsigned)W)
                v = *(const float4*)(xb + (size_t)(gh*W + gw)*CC + c0);
            int o = r*35 + cl;
            sIn[0][o] = v.x; sIn[1][o] = v.y; sIn[2][o] = v.z; sIn[3][o] = v.w;
        }
        // splatted weights: OCB x CB x 9 (ull each)
        for (int i = tid; i < OCB*CB*9; i += 256) {
            int oc = i / (CB*9);
            int rem = i - oc*(CB*9);
            sW2[i] = g_w2[((size_t)(oc0 + oc)*CC + c0 + rem/9)*9 + rem%9];
        }
        __syncthreads();

#pragma unroll
        for (int ch = 0; ch < CB; ch++) {
            ull r2a[9], r2b[9];
#pragma unroll
            for (int t = 0; t < 9; t++) {
                int dy = t/3, dx = t%3;
                int base = (ty + dy)*35 + tx + dx;
                r2a[t] = f2pk(sIn[ch][base],        sIn[ch][base + 8*35]);
                r2b[t] = f2pk(sIn[ch][base + 16*35], sIn[ch][base + 24*35]);
            }
#pragma unroll
            for (int oc = 0; oc < OCB; oc++) {
                const ull* wp2 = &sW2[oc*CB*9 + ch*9];
#pragma unroll
                for (int t = 0; t < 9; t++) {
                    ull w2 = wp2[t];
                    f2fma(accA[oc], w2, r2a[t]);
                    f2fma(accB[oc], w2, r2b[t]);
                }
            }
        }
    }
    int h0 = ty0 + ty, w0 = tx0 + tx;
    size_t pbase = ((size_t)cs*NB + b)*(size_t)OMC*HW;
    bool wok = (w0 < W);
#pragma unroll
    for (int oc = 0; oc < OCB; oc++) {
        float2 a = f2up(accA[oc]);
        float2 c2 = f2up(accB[oc]);
        size_t o = pbase + (size_t)(oc0+oc)*HW;
        if (wok && h0      < H) g_omp[o + (h0     )*W + w0] = a.x;
        if (wok && h0 + 8  < H) g_omp[o + (h0 +  8)*W + w0] = a.y;
        if (wok && h0 + 16 < H) g_omp[o + (h0 + 16)*W + w0] = c2.x;
        if (wok && h0 + 24 < H) g_omp[o + (h0 + 24)*W + w0] = c2.y;
    }
}

// reduce channel-split partials + bias
__global__ __launch_bounds__(256) void k_omred(const float* __restrict__ bom,
                                               int HW, int CS) {
    int idx = blockIdx.x*256 + threadIdx.x;
    int tot = NB*OMC*HW;
    if (idx >= tot) return;
    int oc = (idx / HW) % OMC;
    int b  = idx / (OMC*HW);
    int rem = idx - b*OMC*HW;
    float s = bom[oc];
    for (int cs = 0; cs < CS; cs++)
        s += g_omp[((size_t)cs*NB + b)*(size_t)OMC*HW + rem];
    g_om[idx] = s;
}

// ---------------- DCNv4 bilinear gather (float2 channels, f32x2 math) -------
__global__ __launch_bounds__(256) void k_dcn(int H, int W) {
    int HW = H*W;
    int warp = threadIdx.x >> 5, lane = threadIdx.x & 31;
    int hw = blockIdx.x*8 + warp;
    if (hw >= HW) return;
    int g = blockIdx.y, b = blockIdx.z;
    int h = hw / W, w = hw % W;
    const float* omb = g_om + (size_t)b*OMC*HW;
    const float* xb  = g_xt + (size_t)b*HW*CC + g*64;
    ull acc = 0ull;
#pragma unroll
    for (int k = 0; k < 9; k++) {
        int ky = k/3 - 1, kx = k%3 - 1;
        int ch = (g*9 + k)*3;
        float offy = omb[(size_t)(ch+0)*HW + hw];
        float offx = omb[(size_t)(ch+1)*HW + hw];
        float msk  = omb[(size_t)(ch+2)*HW + hw];
        float py = (float)(h + ky) + offy;
        float px = (float)(w + kx) + offx;
        float y0f = floorf(py), x0f = floorf(px);
        float fy = py - y0f, fx = px - x0f;
        int y0 = (int)y0f, x0 = (int)x0f;
#pragma unroll
        for (int t = 0; t < 4; t++) {
            int dy = t >> 1, dx = t & 1;
            int yy = y0 + dy, xx = x0 + dx;
            float wgt = (dy ? fy : 1.f - fy) * (dx ? fx : 1.f - fx);
            bool valid = (yy >= 0) && (yy < H) && (xx >= 0) && (xx < W);
            float weff = valid ? wgt * msk : 0.f;
            if (weff != 0.f) {                 // warp-uniform branch
                int yc = min(max(yy, 0), H-1);
                int xc = min(max(xx, 0), W-1);
                const ull* p = (const ull*)(xb + (size_t)(yc*W + xc)*CC);
                f2fma(acc, f2pk(weff, weff), p[lane]);
            }
        }
    }
    ((ull*)(g_dcn + ((size_t)b*HW + hw)*CC + g*64))[lane] = acc;
}

// ---------------- 1x1 projection GEMM (f32x2, dense-swizzled) ----------------
// D[m][n] = dcn[m][k] * wp[n][k] + bp[n]; tile 128m x 64n, micro 8m x 4n
__global__ __launch_bounds__(256,2) void k_proj(const float* __restrict__ wp,
                                                const float* __restrict__ bp) {
    __shared__ float As[16][128];
    __shared__ ull   Bs2[16][64];
    int tid = threadIdx.x;
    int m0 = blockIdx.x*128, n0 = blockIdx.y*64;
    ull acc[4][4];
#pragma unroll
    for (int i = 0; i < 4; i++)
#pragma unroll
        for (int j = 0; j < 4; j++) acc[i][j] = 0ull;
    int lm = tid >> 1, lkq = (tid & 1)*8;
    int ln = tid >> 2, lk4 = (tid & 3)*4;
    int tm = tid >> 4, tn = tid & 15;
    for (int k0 = 0; k0 < CC; k0 += 16) {
        float4 a0 = *(const float4*)(g_dcn + (size_t)(m0+lm)*CC + k0 + lkq);
        float4 a1 = *(const float4*)(g_dcn + (size_t)(m0+lm)*CC + k0 + lkq + 4);
        float4 bv = *(const float4*)(wp    + (size_t)(n0+ln)*CC + k0 + lk4);
        __syncthreads();
        As[lkq+0][lm] = a0.x; As[lkq+1][lm] = a0.y; As[lkq+2][lm] = a0.z; As[lkq+3][lm] = a0.w;
        As[lkq+4][lm] = a1.x; As[lkq+5][lm] = a1.y; As[lkq+6][lm] = a1.z; As[lkq+7][lm] = a1.w;
        Bs2[lk4+0][ln] = f2pk(bv.x, bv.x);
        Bs2[lk4+1][ln] = f2pk(bv.y, bv.y);
        Bs2[lk4+2][ln] = f2pk(bv.z, bv.z);
        Bs2[lk4+3][ln] = f2pk(bv.w, bv.w);
        __syncthreads();
#pragma unroll
        for (int kk = 0; kk < 16; kk++) {
            ull ra[4], rb[4];
#pragma unroll
            for (int i = 0; i < 4; i++) ra[i] = *(const ull*)&As[kk][2*tm + 32*i];
#pragma unroll
            for (int j = 0; j < 4; j++) rb[j] = Bs2[kk][tn + 16*j];
#pragma unroll
            for (int i = 0; i < 4; i++)
#pragma unroll
                for (int j = 0; j < 4; j++) f2fma(acc[i][j], ra[i], rb[j]);
        }
    }
#pragma unroll
    for (int i = 0; i < 4; i++)
#pragma unroll
        for (int j = 0; j < 4; j++) {
            float2 v = f2up(acc[i][j]);
            int mm = m0 + 2*tm + 32*i, nn = n0 + tn + 16*j;
            float bia = bp[nn];
            g_d[(size_t)mm*CC + nn]     = v.x + bia;
            g_d[(size_t)(mm+1)*CC + nn] = v.y + bia;
        }
}

// ---------------- channel LayerNorm + sigmoid gate --------------------------
__global__ __launch_bounds__(256) void k_lngate(const float* __restrict__ lng,
                                                const float* __restrict__ lnb, int HW) {
    int r = blockIdx.x;
    int c = threadIdx.x;
    size_t base = (size_t)r*CC;
    float v = g_d[base + c];
    float s1 = v, s2 = v*v;
    __shared__ float sm1[8], sm2[8];
    __shared__ float stat[2];
    int lane = c & 31, wid = c >> 5;
#pragma unroll
    for (int o = 16; o; o >>= 1) {
        s1 += __shfl_down_sync(0xffffffffu, s1, o);
        s2 += __shfl_down_sync(0xffffffffu, s2, o);
    }
    if (!lane) { sm1[wid] = s1; sm2[wid] = s2; }
    __syncthreads();
    if (c == 0) {
        float a = 0.f, q = 0.f;
#pragma unroll
        for (int i = 0; i < 8; i++) { a += sm1[i]; q += sm2[i]; }
        float mu = a * (1.f/CC);
        stat[0] = mu;
        stat[1] = q * (1.f/CC) - mu*mu;
    }
    __syncthreads();
    float mu = stat[0], var = stat[1];
    float dn = (v - mu) * rsqrtf(var + 1e-5f) * lng[c] + lnb[c];
    float gate = 1.f / (1.f + expf(-dn));
    g_x2t[base + c] = g_xt[base + c] * gate;
}

// ---------------- task attention --------------------------------------------
__global__ __launch_bounds__(256) void k_pool2a(int HW, int nSlab) {
    int b = blockIdx.y, slab = blockIdx.x;
    int c = threadIdx.x;
    int rows = HW / nSlab;
    int r0 = slab * rows;
    float s = 0.f;
    for (int r = r0; r < r0 + rows; r++)
        s += g_x2t[((size_t)b*HW + r)*CC + c];
    g_part[(b*16 + slab)*CC + c] = s;
}

__global__ __launch_bounds__(256) void k_pool2b(int HW, int nSlab) {
    int b = blockIdx.x, c = threadIdx.x;
    float s = 0.f;
    for (int i = 0; i < nSlab; i++) s += g_part[(b*16 + i)*CC + c];
    g_pool2[b*CC + c] = s / (float)HW;
}

__global__ __launch_bounds__(256) void k_task_gemv(
        const float* __restrict__ wa1, const float* __restrict__ ba1,
        const float* __restrict__ wb1, const float* __restrict__ bb1,
        const float* __restrict__ wa2, const float* __restrict__ ba2,
        const float* __restrict__ wb2, const float* __restrict__ bb2) {
    int gw = (blockIdx.x*blockDim.x + threadIdx.x) >> 5;
    int lane = threadIdx.x & 31;
    if (gw >= 4*NB*CC) return;
    int which = gw / (NB*CC);
    int rem = gw % (NB*CC);
    int b = rem / CC, o = rem % CC;
    const float* ws = (which == 0) ? wa1 : (which == 1) ? wb1 : (which == 2) ? wa2 : wb2;
    const float* bs = (which == 0) ? ba1 : (which == 1) ? bb1 : (which == 2) ? ba2 : bb2;
    const float* wr = ws + (size_t)o*CC;
    const float* pr = g_pool2 + b*CC;
    float s = 0.f;
#pragma unroll
    for (int i = 0; i < CC/32; i++) s = fmaf(wr[lane + i*32], pr[lane + i*32], s);
#pragma unroll
    for (int o2 = 16; o2; o2 >>= 1) s += __shfl_down_sync(0xffffffffu, s, o2);
    if (!lane) g_ab[which*NB*CC + b*CC + o] = fmaxf(s + bs[o], 0.f);
}

// gated output + transpose back to [b][c][hw]
__global__ __launch_bounds__(256) void k_taskout(float* __restrict__ out, int HW) {
    __shared__ float t[32][33];
    int b = blockIdx.z;
    int hw0 = blockIdx.x*32, c0 = blockIdx.y*32;
    int tx = threadIdx.x, ty = threadIdx.y;   // 32 x 8
#pragma unroll
    for (int i = 0; i < 4; i++) {
        int hw = hw0 + ty + i*8, c = c0 + tx;
        float v  = g_x2t[((size_t)b*HW + hw)*CC + c];
        float A1 = g_ab[0*NB*CC + b*CC + c];
        float B1 = g_ab[1*NB*CC + b*CC + c];
        float A2 = g_ab[2*NB*CC + b*CC + c];
        float B2 = g_ab[3*NB*CC + b*CC + c];
        t[tx][ty + i*8] = fmaxf(fmaf(A1, v, B1), fmaf(A2, v, B2));
    }
    __syncthreads();
#pragma unroll
    for (int i = 0; i < 4; i++) {
        int c = c0 + ty + i*8, hw = hw0 + tx;
        out[((size_t)b*CC + c)*HW + hw] = t[ty + i*8][tx];
    }
}

// ---------------- launch ------------------------------------------------------
extern "C" void kernel_launch(void* const* d_in, const int* in_sizes, int n_in,
                              void* d_out, int out_size) {
    const float* f[3] = { (const float*)d_in[0], (const float*)d_in[1], (const float*)d_in[2] };
    const float* w_scale = (const float*)d_in[3];
    const float* b_scale = (const float*)d_in[4];
    const float* w_om    = (const float*)d_in[5];
    const float* b_om    = (const float*)d_in[6];
    const float* w_proj  = (const float*)d_in[7];
    const float* b_proj  = (const float*)d_in[8];
    const float* ln_g    = (const float*)d_in[9];
    const float* ln_b    = (const float*)d_in[10];
    const float* wa1 = (const float*)d_in[11];
    const float* ba1 = (const float*)d_in[12];
    const float* wb1 = (const float*)d_in[13];
    const float* bb1 = (const float*)d_in[14];
    const float* wa2 = (const float*)d_in[15];
    const float* ba2 = (const float*)d_in[16];
    const float* wb2 = (const float*)d_in[17];
    const float* bb2 = (const float*)d_in[18];
    float* out = (float*)d_out;

    k_wprep<<<(OMC*CC*9 + 255)/256, 256>>>(w_om);

    const int Hs[3] = {64, 32, 16};
    const int CSs[3] = {4, 16, 16};
    size_t ooff = 0;
    for (int s = 0; s < 3; s++) {
        int H = Hs[s], W = Hs[s], HW = H*W;
        int M = NB*HW;
        int CS = CSs[s];
        int nSlab = HW >= 4096 ? 16 : (HW >= 1024 ? 4 : 1);

        k_pool<<<dim3(CC, NB), 256>>>(f[s], HW);
        k_scale_gemv<<<(NB*CC*32 + 255)/256, 256>>>(w_scale, b_scale);
        k_apply<<<dim3(HW/256, CC, NB), 256>>>(f[s], HW);
        k_conv3x3<<<dim3((W+31)/32, (H+31)/32, NB*NOCB*CS), 256>>>(H, W, CS);
        k_omred<<<(NB*OMC*HW + 255)/256, 256>>>(b_om, HW, CS);
        k_dcn<<<dim3(HW/8, GG, NB), 256>>>(H, W);
        k_proj<<<dim3(M/128, CC/64), 256>>>(w_proj, b_proj);
        k_lngate<<<M, 256>>>(ln_g, ln_b, HW);
        k_pool2a<<<dim3(nSlab, NB), 256>>>(HW, nSlab);
        k_pool2b<<<NB, 256>>>(HW, nSlab);
        k_task_gemv<<<(4*NB*CC*32 + 255)/256, 256>>>(wa1, ba1, wb1, bb1, wa2, ba2, wb2, bb2);
        k_taskout<<<dim3(HW/32, CC/32, NB), dim3(32, 8)>>>(out + ooff, HW);

        ooff += (size_t)NB*CC*HW;
    }
}

// round 4
// speedup vs baseline: 3.1656x; 1.1013x over previous
#include <cuda_runtime.h>
#include <math.h>

#define CC    256
#define GG    4
#define NB    2
#define OMC   108          // G*K*3
#define MAXHW 4096
#define OCB   12           // out-channels per conv block (6 pairs)
#define OCP   6            // oc-pairs per conv block
#define NOCB  9            // 108 / 12
#define CB    4            // channels per conv inner batch
#define CSMAX 16

typedef unsigned long long ull;

__device__ __forceinline__ ull f2pk(float lo, float hi) {
    ull r; asm("mov.b64 %0, {%1, %2};" : "=l"(r) : "f"(lo), "f"(hi)); return r;
}
__device__ __forceinline__ void f2fma(ull &d, ull a, ull b) {
    asm("fma.rn.f32x2 %0, %1, %2, %0;" : "+l"(d) : "l"(a), "l"(b));
}
__device__ __forceinline__ float2 f2up(ull v) {
    float2 o; asm("mov.b64 {%0, %1}, %2;" : "=f"(o.x), "=f"(o.y) : "l"(v)); return o;
}

// ---------------- scratch (static device globals; no runtime allocation) ----
__device__ float g_xt [NB*MAXHW*CC];     // scaled input, pixel-major  [b][hw][c]
__device__ float g_om [NB*OMC*MAXHW];    // offset/mask conv output
__device__ float g_omp[CSMAX*NB*OMC*MAXHW]; // conv partials (channel split)
__device__ float g_dcn[NB*MAXHW*CC];     // dcn gather output [b*hw][c]
__device__ float g_d  [NB*MAXHW*CC];     // proj output       [b*hw][c]
__device__ float g_x2t[NB*MAXHW*CC];     // after spatial gate [b*hw][c]
__device__ ull   g_wp [(OMC/2)*CC*9];    // conv weights packed {w_oc, w_oc+1}
__device__ float g_pool [NB*CC];
__device__ float g_sfac [NB*CC];
__device__ float g_part [NB*16*CC];
__device__ float g_pool2[NB*CC];
__device__ float g_ab [4*NB*CC];         // a1,b1,a2,b2

// ---------------- weight pair-pack prep --------------------------------------
__global__ __launch_bounds__(256) void k_wprep(const float* __restrict__ wom) {
    int i = blockIdx.x*256 + threadIdx.x;
    if (i < (OMC/2)*CC*9) {
        int op = i / (CC*9), rem = i % (CC*9);
        g_wp[i] = f2pk(wom[(size_t)(2*op)*CC*9 + rem], wom[(size_t)(2*op+1)*CC*9 + rem]);
    }
}

// ---------------- stage A: channel scale attention --------------------------
__global__ __launch_bounds__(256) void k_pool(const float* __restrict__ x, int HW) {
    int c = blockIdx.x, b = blockIdx.y;
    const float* p = x + ((size_t)b*CC + c)*HW;
    float s = 0.f;
    for (int i = threadIdx.x; i < HW; i += 256) s += p[i];
    __shared__ float sm[8];
    int lane = threadIdx.x & 31, wid = threadIdx.x >> 5;
#pragma unroll
    for (int o = 16; o; o >>= 1) s += __shfl_down_sync(0xffffffffu, s, o);
    if (!lane) sm[wid] = s;
    __syncthreads();
    if (threadIdx.x == 0) {
        float t = 0.f;
#pragma unroll
        for (int i = 0; i < 8; i++) t += sm[i];
        g_pool[b*CC + c] = t / (float)HW;
    }
}

__global__ __launch_bounds__(256) void k_scale_gemv(const float* __restrict__ wsc,
                                                    const float* __restrict__ bsc) {
    int gw = (blockIdx.x*blockDim.x + threadIdx.x) >> 5;
    int lane = threadIdx.x & 31;
    if (gw >= NB*CC) return;
    int b = gw / CC, o = gw % CC;
    const float* wr = wsc + (size_t)o*CC;
    const float* pr = g_pool + b*CC;
    float s = 0.f;
#pragma unroll
    for (int i = 0; i < CC/32; i++) s = fmaf(wr[lane + i*32], pr[lane + i*32], s);
#pragma unroll
    for (int o2 = 16; o2; o2 >>= 1) s += __shfl_down_sync(0xffffffffu, s, o2);
    if (!lane) {
        s = (s + bsc[o] + 1.f) * 0.5f;
        g_sfac[b*CC + o] = fminf(fmaxf(s, 0.f), 1.f);
    }
}

// scale + transpose to pixel-major, both sides coalesced
__global__ __launch_bounds__(256) void k_apply(const float* __restrict__ x, int HW) {
    __shared__ float t[32][33];
    int b = blockIdx.z;
    int hw0 = blockIdx.x*32, c0 = blockIdx.y*32;
    int tx = threadIdx.x, ty = threadIdx.y;     // 32 x 8
#pragma unroll
    for (int i = 0; i < 4; i++) {
        int c = c0 + ty + i*8;
        t[ty + i*8][tx] = x[((size_t)b*CC + c)*HW + hw0 + tx] * g_sfac[b*CC + c];
    }
    __syncthreads();
#pragma unroll
    for (int i = 0; i < 4; i++) {
        int hw = hw0 + ty + i*8;
        g_xt[((size_t)b*HW + hw)*CC + c0 + tx] = t[tx][ty + i*8];
    }
}

// ---------------- 3x3 conv producing offsets/masks --------------------------
// tile 32x16, 256 threads, 2 px/thread (rows ty, ty+8), 6 oc-pairs via f32x2,
// CB channels per inner batch, CS-way channel split.
__global__ __launch_bounds__(256,2) void k_conv3x3(int H, int W, int CS) {
    int HW = H*W;
    int tx0 = blockIdx.x*32, ty0 = blockIdx.y*16;
    int zb = blockIdx.z;
    int cs = zb % CS;
    int rest = zb / CS;
    int b = rest / NOCB, ocb = rest % NOCB;
    int cbase = cs * (CC/CS), cend = cbase + CC/CS;

    __shared__ float sIn[CB][18*35];
    __shared__ ull sW[OCP][CB*9];

    int tid = threadIdx.x;
    int tx = tid & 31, ty = tid >> 5;          // ty in 0..7
    ull a0[OCP], a1[OCP];
#pragma unroll
    for (int i = 0; i < OCP; i++) { a0[i] = 0ull; a1[i] = 0ull; }

    const float* xb = g_xt + (size_t)b*HW*CC;

    for (int c0 = cbase; c0 < cend; c0 += CB) {
        __syncthreads();
        // halo 18x34, 4 channels at once via float4 from pixel-major g_xt
        for (int i = tid; i < 18*34; i += 256) {
            int r = i / 34, cl = i - r*34;
            int gh = ty0 + r - 1, gw = tx0 + cl - 1;
            float4 v = make_float4(0.f, 0.f, 0.f, 0.f);
            if ((unsigned)gh < (unsigned)H && (unsigned)gw < (unsigned)W)
                v = *(const float4*)(xb + (size_t)(gh*W + gw)*CC + c0);
            int o = r*35 + cl;
            sIn[0][o] = v.x; sIn[1][o] = v.y; sIn[2][o] = v.z; sIn[3][o] = v.w;
        }
        // packed weights: OCP x CB x 9 (ull each)
        for (int i = tid; i < OCP*CB*9; i += 256) {
            int p = i / (CB*9);
            int rem = i - p*(CB*9);
            sW[p][rem] = g_wp[((size_t)(ocb*OCP + p)*CC + c0 + rem/9)*9 + rem%9];
        }
        __syncthreads();

#pragma unroll
        for (int ch = 0; ch < CB; ch++) {
#pragma unroll
            for (int t = 0; t < 9; t++) {
                int dy = t/3, dx = t%3;
                int base = (ty + dy)*35 + tx + dx;
                float v0 = sIn[ch][base];
                float v1 = sIn[ch][base + 8*35];
                ull i0 = f2pk(v0, v0);
                ull i1 = f2pk(v1, v1);
#pragma unroll
                for (int p = 0; p < OCP; p++) {
                    ull w = sW[p][ch*9 + t];
                    f2fma(a0[p], w, i0);
                    f2fma(a1[p], w, i1);
                }
            }
        }
    }
    int h0 = ty0 + ty, w0 = tx0 + tx;
    size_t pbase = ((size_t)cs*NB + b)*(size_t)OMC*HW;
    if (w0 < W) {
#pragma unroll
        for (int p = 0; p < OCP; p++) {
            int oc = ocb*OCB + 2*p;
            float2 v = f2up(a0[p]);
            float2 u = f2up(a1[p]);
            if (h0 < H) {
                g_omp[pbase + (size_t)(oc  )*HW + h0*W + w0] = v.x;
                g_omp[pbase + (size_t)(oc+1)*HW + h0*W + w0] = v.y;
            }
            if (h0 + 8 < H) {
                g_omp[pbase + (size_t)(oc  )*HW + (h0+8)*W + w0] = u.x;
                g_omp[pbase + (size_t)(oc+1)*HW + (h0+8)*W + w0] = u.y;
            }
        }
    }
}

// reduce channel-split partials + bias (float4)
__global__ __launch_bounds__(256) void k_omred(const float* __restrict__ bom,
                                               int HW, int CS) {
    int i4 = blockIdx.x*256 + threadIdx.x;
    int tot4 = NB*OMC*HW/4;
    if (i4 >= tot4) return;
    int e = i4*4;
    int oc = (e / HW) % OMC;
    int b  = e / (OMC*HW);
    int rem = e - b*OMC*HW;
    float bia = bom[oc];
    float4 s = make_float4(bia, bia, bia, bia);
    for (int cs = 0; cs < CS; cs++) {
        float4 p = *(const float4*)(g_omp + ((size_t)cs*NB + b)*(size_t)OMC*HW + rem);
        s.x += p.x; s.y += p.y; s.z += p.z; s.w += p.w;
    }
    *(float4*)(g_om + (size_t)e) = s;
}

// ---------------- DCNv4 bilinear gather (float2 channels, f32x2 math) -------
__global__ __launch_bounds__(256) void k_dcn(int H, int W) {
    int HW = H*W;
    int warp = threadIdx.x >> 5, lane = threadIdx.x & 31;
    int hw = blockIdx.x*8 + warp;
    if (hw >= HW) return;
    int g = blockIdx.y, b = blockIdx.z;
    int h = hw / W, w = hw % W;
    const float* omb = g_om + (size_t)b*OMC*HW;
    const float* xb  = g_xt + (size_t)b*HW*CC + g*64;
    ull acc = 0ull;
#pragma unroll
    for (int k = 0; k < 9; k++) {
        int ky = k/3 - 1, kx = k%3 - 1;
        int ch = (g*9 + k)*3;
        float offy = omb[(size_t)(ch+0)*HW + hw];
        float offx = omb[(size_t)(ch+1)*HW + hw];
        float msk  = omb[(size_t)(ch+2)*HW + hw];
        float py = (float)(h + ky) + offy;
        float px = (float)(w + kx) + offx;
        float y0f = floorf(py), x0f = floorf(px);
        float fy = py - y0f, fx = px - x0f;
        int y0 = (int)y0f, x0 = (int)x0f;
#pragma unroll
        for (int t = 0; t < 4; t++) {
            int dy = t >> 1, dx = t & 1;
            int yy = y0 + dy, xx = x0 + dx;
            float wgt = (dy ? fy : 1.f - fy) * (dx ? fx : 1.f - fx);
            bool valid = (yy >= 0) && (yy < H) && (xx >= 0) && (xx < W);
            float weff = valid ? wgt * msk : 0.f;
            if (weff != 0.f) {                 // warp-uniform branch
                int yc = min(max(yy, 0), H-1);
                int xc = min(max(xx, 0), W-1);
                const ull* p = (const ull*)(xb + (size_t)(yc*W + xc)*CC);
                f2fma(acc, f2pk(weff, weff), p[lane]);
            }
        }
    }
    ((ull*)(g_dcn + ((size_t)b*HW + hw)*CC + g*64))[lane] = acc;
}

// ---------------- 1x1 projection GEMM (f32x2, dense-swizzled) ----------------
__global__ __launch_bounds__(256,2) void k_proj(const float* __restrict__ wp,
                                                const float* __restrict__ bp) {
    __shared__ float As[16][128];
    __shared__ ull   Bs2[16][64];
    int tid = threadIdx.x;
    int m0 = blockIdx.x*128, n0 = blockIdx.y*64;
    ull acc[4][4];
#pragma unroll
    for (int i = 0; i < 4; i++)
#pragma unroll
        for (int j = 0; j < 4; j++) acc[i][j] = 0ull;
    int lm = tid >> 1, lkq = (tid & 1)*8;
    int ln = tid >> 2, lk4 = (tid & 3)*4;
    int tm = tid >> 4, tn = tid & 15;
    for (int k0 = 0; k0 < CC; k0 += 16) {
        float4 aq0 = *(const float4*)(g_dcn + (size_t)(m0+lm)*CC + k0 + lkq);
        float4 aq1 = *(const float4*)(g_dcn + (size_t)(m0+lm)*CC + k0 + lkq + 4);
        float4 bv = *(const float4*)(wp    + (size_t)(n0+ln)*CC + k0 + lk4);
        __syncthreads();
        As[lkq+0][lm] = aq0.x; As[lkq+1][lm] = aq0.y; As[lkq+2][lm] = aq0.z; As[lkq+3][lm] = aq0.w;
        As[lkq+4][lm] = aq1.x; As[lkq+5][lm] = aq1.y; As[lkq+6][lm] = aq1.z; As[lkq+7][lm] = aq1.w;
        Bs2[lk4+0][ln] = f2pk(bv.x, bv.x);
        Bs2[lk4+1][ln] = f2pk(bv.y, bv.y);
        Bs2[lk4+2][ln] = f2pk(bv.z, bv.z);
        Bs2[lk4+3][ln] = f2pk(bv.w, bv.w);
        __syncthreads();
#pragma unroll
        for (int kk = 0; kk < 16; kk++) {
            ull ra[4], rb[4];
#pragma unroll
            for (int i = 0; i < 4; i++) ra[i] = *(const ull*)&As[kk][2*tm + 32*i];
#pragma unroll
            for (int j = 0; j < 4; j++) rb[j] = Bs2[kk][tn + 16*j];
#pragma unroll
            for (int i = 0; i < 4; i++)
#pragma unroll
                for (int j = 0; j < 4; j++) f2fma(acc[i][j], ra[i], rb[j]);
        }
    }
#pragma unroll
    for (int i = 0; i < 4; i++)
#pragma unroll
        for (int j = 0; j < 4; j++) {
            float2 v = f2up(acc[i][j]);
            int mm = m0 + 2*tm + 32*i, nn = n0 + tn + 16*j;
            float bia = bp[nn];
            g_d[(size_t)mm*CC + nn]     = v.x + bia;
            g_d[(size_t)(mm+1)*CC + nn] = v.y + bia;
        }
}

// ---------------- channel LayerNorm + sigmoid gate (warp per row) ------------
__global__ __launch_bounds__(256) void k_lngate(const float* __restrict__ lng,
                                                const float* __restrict__ lnb) {
    int warp = threadIdx.x >> 5, lane = threadIdx.x & 31;
    int r = blockIdx.x*8 + warp;
    size_t base = (size_t)r*CC;
    float4 v0 = *(const float4*)(g_d + base + lane*8);
    float4 v1 = *(const float4*)(g_d + base + lane*8 + 4);
    float s = v0.x+v0.y+v0.z+v0.w + v1.x+v1.y+v1.z+v1.w;
    float q = v0.x*v0.x+v0.y*v0.y+v0.z*v0.z+v0.w*v0.w
            + v1.x*v1.x+v1.y*v1.y+v1.z*v1.z+v1.w*v1.w;
#pragma unroll
    for (int o = 16; o; o >>= 1) {
        s += __shfl_xor_sync(0xffffffffu, s, o);
        q += __shfl_xor_sync(0xffffffffu, q, o);
    }
    float mu = s * (1.f/CC);
    float rs = rsqrtf(q * (1.f/CC) - mu*mu + 1e-5f);
    float4 g0 = *(const float4*)(lng + lane*8);
    float4 g1 = *(const float4*)(lng + lane*8 + 4);
    float4 b0 = *(const float4*)(lnb + lane*8);
    float4 b1 = *(const float4*)(lnb + lane*8 + 4);
    float4 x0 = *(const float4*)(g_xt + base + lane*8);
    float4 x1 = *(const float4*)(g_xt + base + lane*8 + 4);
    float4 o0, o1;
    o0.x = x0.x / (1.f + expf(-((v0.x-mu)*rs*g0.x + b0.x)));
    o0.y = x0.y / (1.f + expf(-((v0.y-mu)*rs*g0.y + b0.y)));
    o0.z = x0.z / (1.f + expf(-((v0.z-mu)*rs*g0.z + b0.z)));
    o0.w = x0.w / (1.f + expf(-((v0.w-mu)*rs*g0.w + b0.w)));
    o1.x = x1.x / (1.f + expf(-((v1.x-mu)*rs*g1.x + b1.x)));
    o1.y = x1.y / (1.f + expf(-((v1.y-mu)*rs*g1.y + b1.y)));
    o1.z = x1.z / (1.f + expf(-((v1.z-mu)*rs*g1.z + b1.z)));
    o1.w = x1.w / (1.f + expf(-((v1.w-mu)*rs*g1.w + b1.w)));
    *(float4*)(g_x2t + base + lane*8)     = o0;
    *(float4*)(g_x2t + base + lane*8 + 4) = o1;
}

// ---------------- task attention --------------------------------------------
__global__ __launch_bounds__(256) void k_pool2a(int HW, int nSlab) {
    int b = blockIdx.y, slab = blockIdx.x;
    int c = threadIdx.x;
    int rows = HW / nSlab;
    int r0 = slab * rows;
    float s = 0.f;
    for (int r = r0; r < r0 + rows; r++)
        s += g_x2t[((size_t)b*HW + r)*CC + c];
    g_part[(b*16 + slab)*CC + c] = s;
}

__global__ __launch_bounds__(256) void k_pool2b(int HW, int nSlab) {
    int b = blockIdx.x, c = threadIdx.x;
    float s = 0.f;
    for (int i = 0; i < nSlab; i++) s += g_part[(b*16 + i)*CC + c];
    g_pool2[b*CC + c] = s / (float)HW;
}

__global__ __launch_bounds__(256) void k_task_gemv(
        const float* __restrict__ wa1, const float* __restrict__ ba1,
        const float* __restrict__ wb1, const float* __restrict__ bb1,
        const float* __restrict__ wa2, const float* __restrict__ ba2,
        const float* __restrict__ wb2, const float* __restrict__ bb2) {
    int gw = (blockIdx.x*blockDim.x + threadIdx.x) >> 5;
    int lane = threadIdx.x & 31;
    if (gw >= 4*NB*CC) return;
    int which = gw / (NB*CC);
    int rem = gw % (NB*CC);
    int b = rem / CC, o = rem % CC;
    const float* ws = (which == 0) ? wa1 : (which == 1) ? wb1 : (which == 2) ? wa2 : wb2;
    const float* bs = (which == 0) ? ba1 : (which == 1) ? bb1 : (which == 2) ? ba2 : bb2;
    const float* wr = ws + (size_t)o*CC;
    const float* pr = g_pool2 + b*CC;
    float s = 0.f;
#pragma unroll
    for (int i = 0; i < CC/32; i++) s = fmaf(wr[lane + i*32], pr[lane + i*32], s);
#pragma unroll
    for (int o2 = 16; o2; o2 >>= 1) s += __shfl_down_sync(0xffffffffu, s, o2);
    if (!lane) g_ab[which*NB*CC + b*CC + o] = fmaxf(s + bs[o], 0.f);
}

// gated output + transpose back to [b][c][hw]
__global__ __launch_bounds__(256) void k_taskout(float* __restrict__ out, int HW) {
    __shared__ float t[32][33];
    int b = blockIdx.z;
    int hw0 = blockIdx.x*32, c0 = blockIdx.y*32;
    int tx = threadIdx.x, ty = threadIdx.y;   // 32 x 8
#pragma unroll
    for (int i = 0; i < 4; i++) {
        int hw = hw0 + ty + i*8, c = c0 + tx;
        float v  = g_x2t[((size_t)b*HW + hw)*CC + c];
        float A1 = g_ab[0*NB*CC + b*CC + c];
        float B1 = g_ab[1*NB*CC + b*CC + c];
        float A2 = g_ab[2*NB*CC + b*CC + c];
        float B2 = g_ab[3*NB*CC + b*CC + c];
        t[tx][ty + i*8] = fmaxf(fmaf(A1, v, B1), fmaf(A2, v, B2));
    }
    __syncthreads();
#pragma unroll
    for (int i = 0; i < 4; i++) {
        int c = c0 + ty + i*8, hw = hw0 + tx;
        out[((size_t)b*CC + c)*HW + hw] = t[ty + i*8][tx];
    }
}

// ---------------- launch ------------------------------------------------------
extern "C" void kernel_launch(void* const* d_in, const int* in_sizes, int n_in,
                              void* d_out, int out_size) {
    const float* f[3] = { (const float*)d_in[0], (const float*)d_in[1], (const float*)d_in[2] };
    const float* w_scale = (const float*)d_in[3];
    const float* b_scale = (const float*)d_in[4];
    const float* w_om    = (const float*)d_in[5];
    const float* b_om    = (const float*)d_in[6];
    const float* w_proj  = (const float*)d_in[7];
    const float* b_proj  = (const float*)d_in[8];
    const float* ln_g    = (const float*)d_in[9];
    const float* ln_b    = (const float*)d_in[10];
    const float* wa1 = (const float*)d_in[11];
    const float* ba1 = (const float*)d_in[12];
    const float* wb1 = (const float*)d_in[13];
    const float* bb1 = (const float*)d_in[14];
    const float* wa2 = (const float*)d_in[15];
    const float* ba2 = (const float*)d_in[16];
    const float* wb2 = (const float*)d_in[17];
    const float* bb2 = (const float*)d_in[18];
    float* out = (float*)d_out;

    k_wprep<<<((OMC/2)*CC*9 + 255)/256, 256>>>(w_om);

    const int Hs[3] = {64, 32, 16};
    const int CSs[3] = {2, 8, 16};
    size_t ooff = 0;
    for (int s = 0; s < 3; s++) {
        int H = Hs[s], W = Hs[s], HW = H*W;
        int M = NB*HW;
        int CS = CSs[s];
        int nSlab = HW >= 4096 ? 16 : (HW >= 1024 ? 4 : 1);

        k_pool<<<dim3(CC, NB), 256>>>(f[s], HW);
        k_scale_gemv<<<(NB*CC*32 + 255)/256, 256>>>(w_scale, b_scale);
        k_apply<<<dim3(HW/32, CC/32, NB), dim3(32, 8)>>>(f[s], HW);
        k_conv3x3<<<dim3((W+31)/32, (H+15)/16, NB*NOCB*CS), 256>>>(H, W, CS);
        k_omred<<<(NB*OMC*HW/4 + 255)/256, 256>>>(b_om, HW, CS);
        k_dcn<<<dim3(HW/8, GG, NB), 256>>>(H, W);
        k_proj<<<dim3(M/128, CC/64), 256>>>(w_proj, b_proj);
        k_lngate<<<M/8, 256>>>(ln_g, ln_b);
        k_pool2a<<<dim3(nSlab, NB), 256>>>(HW, nSlab);
        k_pool2b<<<NB, 256>>>(HW, nSlab);
        k_task_gemv<<<(4*NB*CC*32 + 255)/256, 256>>>(wa1, ba1, wb1, bb1, wa2, ba2, wb2, bb2);
        k_taskout<<<dim3(HW/32, CC/32, NB), dim3(32, 8)>>>(out + ooff, HW);

        ooff += (size_t)NB*CC*HW;
    }
}

// round 5
// speedup vs baseline: 4.0132x; 1.2678x over previous
#include <cuda_runtime.h>
#include <math.h>

#define CC    256
#define GG    4
#define NB    2
#define OMC   108          // G*K*3
#define TP    5376         // total pixels per batch across scales (4096+1024+256)
#define OCB   12           // out-channels per conv block (6 pairs)
#define OCP   6            // oc-pairs per conv block
#define NOCB  9            // 108 / 12
#define CB    4            // channels per conv inner batch

// per-scale compile-time facts (s = 0,1,2):
//   H=W=64>>s, HW=4096>>(2s), SOFF={0,4096,5120}, CS={2,8,16}
#define SEL3(s,a,b,c) ((s)==0 ? (a) : ((s)==1 ? (b) : (c)))

typedef unsigned long long ull;

__device__ __forceinline__ ull f2pk(float lo, float hi) {
    ull r; asm("mov.b64 %0, {%1, %2};" : "=l"(r) : "f"(lo), "f"(hi)); return r;
}
__device__ __forceinline__ void f2fma(ull &d, ull a, ull b) {
    asm("fma.rn.f32x2 %0, %1, %2, %0;" : "+l"(d) : "l"(a), "l"(b));
}
__device__ __forceinline__ float2 f2up(ull v) {
    float2 o; asm("mov.b64 {%0, %1}, %2;" : "=f"(o.x), "=f"(o.y) : "l"(v)); return o;
}

// ---------------- scratch (static device globals) ---------------------------
__device__ float g_xt [NB*TP*CC];        // scaled input, pixel-major [b][p][c]
__device__ float g_om [NB*OMC*TP];       // offset/mask conv output (per-scale blocks)
__device__ float g_omp[6193152];         // conv partials (channel split, all scales)
__device__ float g_dcn[NB*TP*CC];        // dcn gather output [row][c]
__device__ float g_d  [NB*TP*CC];        // proj output       [row][c]
__device__ float g_x2t[NB*TP*CC];        // after spatial gate [row][c]
__device__ ull   g_wp [(OMC/2)*CC*9];    // conv weights packed {w_oc, w_oc+1}
__device__ float g_pool [3*NB*CC];
__device__ float g_sfac [3*NB*CC];
__device__ float g_part [NB*84*CC];
__device__ float g_pool2[3*NB*CC];
__device__ float g_ab  [4*3*NB*CC];      // [which][s][b][c]

// g_om scale base offsets: NB*OMC*SOFF
#define OMOFF(s) SEL3(s, 0, 884736, 1105920)
// g_omp scale base offsets
#define POFF(s)  SEL3(s, 0, 3538944, 5308416)

// ---------------- weight pair-pack prep --------------------------------------
__global__ __launch_bounds__(256) void k_wprep(const float* __restrict__ wom) {
    int i = blockIdx.x*256 + threadIdx.x;
    if (i < (OMC/2)*CC*9) {
        int op = i / (CC*9), rem = i % (CC*9);
        g_wp[i] = f2pk(wom[(size_t)(2*op)*CC*9 + rem], wom[(size_t)(2*op+1)*CC*9 + rem]);
    }
}

// ---------------- stage A: channel scale attention (all scales) --------------
__global__ __launch_bounds__(256) void k_pool(const float* __restrict__ f1,
                                              const float* __restrict__ f2,
                                              const float* __restrict__ f3) {
    int c = blockIdx.x, b = blockIdx.y, s = blockIdx.z;
    int HW = 4096 >> (2*s);
    const float* x = SEL3(s, f1, f2, f3);
    const float* p = x + ((size_t)b*CC + c)*HW;
    float v = 0.f;
    for (int i = threadIdx.x; i < HW; i += 256) v += p[i];
    __shared__ float sm[8];
    int lane = threadIdx.x & 31, wid = threadIdx.x >> 5;
#pragma unroll
    for (int o = 16; o; o >>= 1) v += __shfl_down_sync(0xffffffffu, v, o);
    if (!lane) sm[wid] = v;
    __syncthreads();
    if (threadIdx.x == 0) {
        float t = 0.f;
#pragma unroll
        for (int i = 0; i < 8; i++) t += sm[i];
        g_pool[(s*NB + b)*CC + c] = t / (float)HW;
    }
}

__global__ __launch_bounds__(256) void k_scale_gemv(const float* __restrict__ wsc,
                                                    const float* __restrict__ bsc) {
    int gw = (blockIdx.x*blockDim.x + threadIdx.x) >> 5;
    int lane = threadIdx.x & 31;
    if (gw >= 3*NB*CC) return;
    int sb = gw / CC, o = gw % CC;       // sb = s*NB + b
    const float* wr = wsc + (size_t)o*CC;
    const float* pr = g_pool + sb*CC;
    float v = 0.f;
#pragma unroll
    for (int i = 0; i < CC/32; i++) v = fmaf(wr[lane + i*32], pr[lane + i*32], v);
#pragma unroll
    for (int o2 = 16; o2; o2 >>= 1) v += __shfl_down_sync(0xffffffffu, v, o2);
    if (!lane) {
        v = (v + bsc[o] + 1.f) * 0.5f;
        g_sfac[sb*CC + o] = fminf(fmaxf(v, 0.f), 1.f);
    }
}

// scale + transpose to pixel-major (all scales; x-tile cum {128,160,168})
__global__ __launch_bounds__(256) void k_apply(const float* __restrict__ f1,
                                               const float* __restrict__ f2,
                                               const float* __restrict__ f3) {
    __shared__ float t[32][33];
    int bx = blockIdx.x;
    int s = (bx >= 128) + (bx >= 160);
    int base = SEL3(s, 0, 128, 160);
    int HW = 4096 >> (2*s);
    int SOFF = SEL3(s, 0, 4096, 5120);
    const float* x = SEL3(s, f1, f2, f3);
    int b = blockIdx.z;
    int hw0 = (bx - base)*32, c0 = blockIdx.y*32;
    int tx = threadIdx.x, ty = threadIdx.y;     // 32 x 8
#pragma unroll
    for (int i = 0; i < 4; i++) {
        int c = c0 + ty + i*8;
        t[ty + i*8][tx] = x[((size_t)b*CC + c)*HW + hw0 + tx] * g_sfac[(s*NB + b)*CC + c];
    }
    __syncthreads();
#pragma unroll
    for (int i = 0; i < 4; i++) {
        int hw = hw0 + ty + i*8;
        g_xt[((size_t)b*TP + SOFF + hw)*CC + c0 + tx] = t[tx][ty + i*8];
    }
}

// ---------------- 3x3 conv producing offsets/masks (all scales) --------------
// 288 blocks per scale, grid.z = 864
__global__ __launch_bounds__(256,2) void k_conv3x3() {
    int z = blockIdx.z;
    int s = z / 288;
    int r = z % 288;
    int CS = SEL3(s, 2, 8, 16);
    int H = 64 >> s, W = 64 >> s, HW = H*W;
    int SOFF = SEL3(s, 0, 4096, 5120);
    int nx = SEL3(s, 2, 1, 1);

    int cs = r % CS;  r /= CS;
    int ocb = r % NOCB; r /= NOCB;
    int b = r % NB;   r /= NB;
    int txi = r % nx, tyi = r / nx;
    int tx0 = txi*32, ty0 = tyi*16;
    int cbase = cs * (CC/CS), cend = cbase + CC/CS;

    __shared__ float sIn[CB][18*35];
    __shared__ ull sW[OCP][CB*9];

    int tid = threadIdx.x;
    int tx = tid & 31, ty = tid >> 5;          // ty in 0..7
    ull a0[OCP], a1[OCP];
#pragma unroll
    for (int i = 0; i < OCP; i++) { a0[i] = 0ull; a1[i] = 0ull; }

    const float* xb = g_xt + ((size_t)b*TP + SOFF)*CC;

    for (int c0 = cbase; c0 < cend; c0 += CB) {
        __syncthreads();
        for (int i = tid; i < 18*34; i += 256) {
            int rr = i / 34, cl = i - rr*34;
            int gh = ty0 + rr - 1, gw = tx0 + cl - 1;
            float4 v = make_float4(0.f, 0.f, 0.f, 0.f);
            if ((unsigned)gh < (unsigned)H && (unsigned)gw < (unsigned)W)
                v = *(const float4*)(xb + (size_t)(gh*W + gw)*CC + c0);
            int o = rr*35 + cl;
            sIn[0][o] = v.x; sIn[1][o] = v.y; sIn[2][o] = v.z; sIn[3][o] = v.w;
        }
        for (int i = tid; i < OCP*CB*9; i += 256) {
            int p = i / (CB*9);
            int rem = i - p*(CB*9);
            sW[p][rem] = g_wp[((size_t)(ocb*OCP + p)*CC + c0 + rem/9)*9 + rem%9];
        }
        __syncthreads();

#pragma unroll
        for (int ch = 0; ch < CB; ch++) {
#pragma unroll
            for (int t = 0; t < 9; t++) {
                int dy = t/3, dx = t%3;
                int bse = (ty + dy)*35 + tx + dx;
                float v0 = sIn[ch][bse];
                float v1 = sIn[ch][bse + 8*35];
                ull i0 = f2pk(v0, v0);
                ull i1 = f2pk(v1, v1);
#pragma unroll
                for (int p = 0; p < OCP; p++) {
                    ull w = sW[p][ch*9 + t];
                    f2fma(a0[p], w, i0);
                    f2fma(a1[p], w, i1);
                }
            }
        }
    }
    int h0 = ty0 + ty, w0 = tx0 + tx;
    size_t pbase = (size_t)POFF(s) + ((size_t)cs*NB + b)*(size_t)OMC*HW;
    if (w0 < W) {
#pragma unroll
        for (int p = 0; p < OCP; p++) {
            int oc = ocb*OCB + 2*p;
            float2 v = f2up(a0[p]);
            float2 u = f2up(a1[p]);
            if (h0 < H) {
                g_omp[pbase + (size_t)(oc  )*HW + h0*W + w0] = v.x;
                g_omp[pbase + (size_t)(oc+1)*HW + h0*W + w0] = v.y;
            }
            if (h0 + 8 < H) {
                g_omp[pbase + (size_t)(oc  )*HW + (h0+8)*W + w0] = u.x;
                g_omp[pbase + (size_t)(oc+1)*HW + (h0+8)*W + w0] = u.y;
            }
        }
    }
}

// reduce channel-split partials + bias (float4); x-cum {864,1080,1134}
__global__ __launch_bounds__(256) void k_omred(const float* __restrict__ bom) {
    int bx = blockIdx.x;
    int s = (bx >= 864) + (bx >= 1080);
    int base = SEL3(s, 0, 864, 1080);
    int CS = SEL3(s, 2, 8, 16);
    int HW = 4096 >> (2*s);
    int e = ((bx - base)*256 + threadIdx.x)*4;
    int b  = e / (OMC*HW);
    int rem = e - b*OMC*HW;
    int oc = rem / HW;
    float bia = bom[oc];
    float4 v = make_float4(bia, bia, bia, bia);
    size_t pb = (size_t)POFF(s);
    for (int cs = 0; cs < CS; cs++) {
        float4 p = *(const float4*)(g_omp + pb + ((size_t)cs*NB + b)*(size_t)OMC*HW + rem);
        v.x += p.x; v.y += p.y; v.z += p.z; v.w += p.w;
    }
    *(float4*)(g_om + OMOFF(s) + (size_t)e) = v;
}

// ---------------- DCNv4 bilinear gather (all scales; x-cum {512,640,672}) ----
__global__ __launch_bounds__(256) void k_dcn() {
    int bx = blockIdx.x;
    int s = (bx >= 512) + (bx >= 640);
    int base = SEL3(s, 0, 512, 640);
    int H = 64 >> s, W = 64 >> s, HW = H*W;
    int SOFF = SEL3(s, 0, 4096, 5120);
    int warp = threadIdx.x >> 5, lane = threadIdx.x & 31;
    int hw = (bx - base)*8 + warp;
    int g = blockIdx.y, b = blockIdx.z;
    int h = hw / W, w = hw % W;
    const float* omb = g_om + OMOFF(s) + (size_t)b*OMC*HW;
    const float* xb  = g_xt + ((size_t)b*TP + SOFF)*CC + g*64;
    ull acc = 0ull;
#pragma unroll
    for (int k = 0; k < 9; k++) {
        int ky = k/3 - 1, kx = k%3 - 1;
        int ch = (g*9 + k)*3;
        float offy = omb[(size_t)(ch+0)*HW + hw];
        float offx = omb[(size_t)(ch+1)*HW + hw];
        float msk  = omb[(size_t)(ch+2)*HW + hw];
        float py = (float)(h + ky) + offy;
        float px = (float)(w + kx) + offx;
        float y0f = floorf(py), x0f = floorf(px);
        float fy = py - y0f, fx = px - x0f;
        int y0 = (int)y0f, x0 = (int)x0f;
#pragma unroll
        for (int t = 0; t < 4; t++) {
            int dy = t >> 1, dx = t & 1;
            int yy = y0 + dy, xx = x0 + dx;
            float wgt = (dy ? fy : 1.f - fy) * (dx ? fx : 1.f - fx);
            bool valid = (yy >= 0) && (yy < H) && (xx >= 0) && (xx < W);
            float weff = valid ? wgt * msk : 0.f;
            if (weff != 0.f) {
                int yc = min(max(yy, 0), H-1);
                int xc = min(max(xx, 0), W-1);
                const ull* p = (const ull*)(xb + (size_t)(yc*W + xc)*CC);
                f2fma(acc, f2pk(weff, weff), p[lane]);
            }
        }
    }
    ((ull*)(g_dcn + ((size_t)b*TP + SOFF + hw)*CC + g*64))[lane] = acc;
}

// ---------------- 1x1 projection GEMM (f32x2); M = NB*TP = 10752 -------------
__global__ __launch_bounds__(256,2) void k_proj(const float* __restrict__ wp,
                                                const float* __restrict__ bp) {
    __shared__ float As[16][128];
    __shared__ ull   Bs2[16][64];
    int tid = threadIdx.x;
    int m0 = blockIdx.x*128, n0 = blockIdx.y*64;
    ull acc[4][4];
#pragma unroll
    for (int i = 0; i < 4; i++)
#pragma unroll
        for (int j = 0; j < 4; j++) acc[i][j] = 0ull;
    int lm = tid >> 1, lkq = (tid & 1)*8;
    int ln = tid >> 2, lk4 = (tid & 3)*4;
    int tm = tid >> 4, tn = tid & 15;
    for (int k0 = 0; k0 < CC; k0 += 16) {
        float4 aq0 = *(const float4*)(g_dcn + (size_t)(m0+lm)*CC + k0 + lkq);
        float4 aq1 = *(const float4*)(g_dcn + (size_t)(m0+lm)*CC + k0 + lkq + 4);
        float4 bv = *(const float4*)(wp    + (size_t)(n0+ln)*CC + k0 + lk4);
        __syncthreads();
        As[lkq+0][lm] = aq0.x; As[lkq+1][lm] = aq0.y; As[lkq+2][lm] = aq0.z; As[lkq+3][lm] = aq0.w;
        As[lkq+4][lm] = aq1.x; As[lkq+5][lm] = aq1.y; As[lkq+6][lm] = aq1.z; As[lkq+7][lm] = aq1.w;
        Bs2[lk4+0][ln] = f2pk(bv.x, bv.x);
        Bs2[lk4+1][ln] = f2pk(bv.y, bv.y);
        Bs2[lk4+2][ln] = f2pk(bv.z, bv.z);
        Bs2[lk4+3][ln] = f2pk(bv.w, bv.w);
        __syncthreads();
#pragma unroll
        for (int kk = 0; kk < 16; kk++) {
            ull ra[4], rb[4];
#pragma unroll
            for (int i = 0; i < 4; i++) ra[i] = *(const ull*)&As[kk][2*tm + 32*i];
#pragma unroll
            for (int j = 0; j < 4; j++) rb[j] = Bs2[kk][tn + 16*j];
#pragma unroll
            for (int i = 0; i < 4; i++)
#pragma unroll
                for (int j = 0; j < 4; j++) f2fma(acc[i][j], ra[i], rb[j]);
        }
    }
#pragma unroll
    for (int i = 0; i < 4; i++)
#pragma unroll
        for (int j = 0; j < 4; j++) {
            float2 v = f2up(acc[i][j]);
            int mm = m0 + 2*tm + 32*i, nn = n0 + tn + 16*j;
            float bia = bp[nn];
            g_d[(size_t)mm*CC + nn]     = v.x + bia;
            g_d[(size_t)(mm+1)*CC + nn] = v.y + bia;
        }
}

// ---------------- channel LayerNorm + sigmoid gate (warp per row) ------------
__global__ __launch_bounds__(256) void k_lngate(const float* __restrict__ lng,
                                                const float* __restrict__ lnb) {
    int warp = threadIdx.x >> 5, lane = threadIdx.x & 31;
    int r = blockIdx.x*8 + warp;
    size_t base = (size_t)r*CC;
    float4 v0 = *(const float4*)(g_d + base + lane*8);
    float4 v1 = *(const float4*)(g_d + base + lane*8 + 4);
    float s = v0.x+v0.y+v0.z+v0.w + v1.x+v1.y+v1.z+v1.w;
    float q = v0.x*v0.x+v0.y*v0.y+v0.z*v0.z+v0.w*v0.w
            + v1.x*v1.x+v1.y*v1.y+v1.z*v1.z+v1.w*v1.w;
#pragma unroll
    for (int o = 16; o; o >>= 1) {
        s += __shfl_xor_sync(0xffffffffu, s, o);
        q += __shfl_xor_sync(0xffffffffu, q, o);
    }
    float mu = s * (1.f/CC);
    float rs = rsqrtf(q * (1.f/CC) - mu*mu + 1e-5f);
    float4 g0 = *(const float4*)(lng + lane*8);
    float4 g1 = *(const float4*)(lng + lane*8 + 4);
    float4 b0 = *(const float4*)(lnb + lane*8);
    float4 b1 = *(const float4*)(lnb + lane*8 + 4);
    float4 x0 = *(const float4*)(g_xt + base + lane*8);
    float4 x1 = *(const float4*)(g_xt + base + lane*8 + 4);
    float4 o0, o1;
    o0.x = x0.x / (1.f + expf(-((v0.x-mu)*rs*g0.x + b0.x)));
    o0.y = x0.y / (1.f + expf(-((v0.y-mu)*rs*g0.y + b0.y)));
    o0.z = x0.z / (1.f + expf(-((v0.z-mu)*rs*g0.z + b0.z)));
    o0.w = x0.w / (1.f + expf(-((v0.w-mu)*rs*g0.w + b0.w)));
    o1.x = x1.x / (1.f + expf(-((v1.x-mu)*rs*g1.x + b1.x)));
    o1.y = x1.y / (1.f + expf(-((v1.y-mu)*rs*g1.y + b1.y)));
    o1.z = x1.z / (1.f + expf(-((v1.z-mu)*rs*g1.z + b1.z)));
    o1.w = x1.w / (1.f + expf(-((v1.w-mu)*rs*g1.w + b1.w)));
    *(float4*)(g_x2t + base + lane*8)     = o0;
    *(float4*)(g_x2t + base + lane*8 + 4) = o1;
}

// ---------------- task attention: pooled mean (64-row slabs; cum {64,80,84}) --
__global__ __launch_bounds__(256) void k_pool2a() {
    int slab = blockIdx.x, b = blockIdx.y;
    int s = (slab >= 64) + (slab >= 80);
    int sbase = SEL3(s, 0, 64, 80);
    int SOFF = SEL3(s, 0, 4096, 5120);
    int c = threadIdx.x;
    int r0 = SOFF + (slab - sbase)*64;
    float v = 0.f;
    for (int r = r0; r < r0 + 64; r++)
        v += g_x2t[((size_t)b*TP + r)*CC + c];
    g_part[(b*84 + slab)*CC + c] = v;
}

__global__ __launch_bounds__(256) void k_pool2b() {
    int s = blockIdx.x, b = blockIdx.y, c = threadIdx.x;
    int slabs = SEL3(s, 64, 16, 4);
    int sbase = SEL3(s, 0, 64, 80);
    int HW = 4096 >> (2*s);
    float v = 0.f;
    for (int i = 0; i < slabs; i++) v += g_part[(b*84 + sbase + i)*CC + c];
    g_pool2[(s*NB + b)*CC + c] = v / (float)HW;
}

__global__ __launch_bounds__(256) void k_task_gemv(
        const float* __restrict__ wa1, const float* __restrict__ ba1,
        const float* __restrict__ wb1, const float* __restrict__ bb1,
        const float* __restrict__ wa2, const float* __restrict__ ba2,
        const float* __restrict__ wb2, const float* __restrict__ bb2) {
    int gw = (blockIdx.x*blockDim.x + threadIdx.x) >> 5;
    int lane = threadIdx.x & 31;
    if (gw >= 4*3*NB*CC) return;
    int which = gw / (3*NB*CC);
    int rem = gw % (3*NB*CC);
    int sb = rem / CC, o = rem % CC;     // sb = s*NB + b
    const float* ws = (which == 0) ? wa1 : (which == 1) ? wb1 : (which == 2) ? wa2 : wb2;
    const float* bs = (which == 0) ? ba1 : (which == 1) ? bb1 : (which == 2) ? ba2 : bb2;
    const float* wr = ws + (size_t)o*CC;
    const float* pr = g_pool2 + sb*CC;
    float v = 0.f;
#pragma unroll
    for (int i = 0; i < CC/32; i++) v = fmaf(wr[lane + i*32], pr[lane + i*32], v);
#pragma unroll
    for (int o2 = 16; o2; o2 >>= 1) v += __shfl_down_sync(0xffffffffu, v, o2);
    if (!lane) g_ab[(which*3*NB + sb)*CC + o] = fmaxf(v + bs[o], 0.f);
}

// gated output + transpose back to per-scale [b][c][hw]; x-cum {128,160,168}
__global__ __launch_bounds__(256) void k_taskout(float* __restrict__ out) {
    __shared__ float t[32][33];
    int bx = blockIdx.x;
    int s = (bx >= 128) + (bx >= 160);
    int base = SEL3(s, 0, 128, 160);
    int HW = 4096 >> (2*s);
    int SOFF = SEL3(s, 0, 4096, 5120);
    size_t OOFF = (size_t)NB*CC*SOFF;
    int b = blockIdx.z;
    int hw0 = (bx - base)*32, c0 = blockIdx.y*32;
    int tx = threadIdx.x, ty = threadIdx.y;   // 32 x 8
    int sb = s*NB + b;
#pragma unroll
    for (int i = 0; i < 4; i++) {
        int hw = hw0 + ty + i*8, c = c0 + tx;
        float v  = g_x2t[((size_t)b*TP + SOFF + hw)*CC + c];
        float A1 = g_ab[(0*3*NB + sb)*CC + c];
        float B1 = g_ab[(1*3*NB + sb)*CC + c];
        float A2 = g_ab[(2*3*NB + sb)*CC + c];
        float B2 = g_ab[(3*3*NB + sb)*CC + c];
        t[tx][ty + i*8] = fmaxf(fmaf(A1, v, B1), fmaf(A2, v, B2));
    }
    __syncthreads();
#pragma unroll
    for (int i = 0; i < 4; i++) {
        int c = c0 + ty + i*8, hw = hw0 + tx;
        out[OOFF + ((size_t)b*CC + c)*HW + hw] = t[ty + i*8][tx];
    }
}

// ---------------- launch ------------------------------------------------------
extern "C" void kernel_launch(void* const* d_in, const int* in_sizes, int n_in,
                              void* d_out, int out_size) {
    const float* f1 = (const float*)d_in[0];
    const float* f2 = (const float*)d_in[1];
    const float* f3 = (const float*)d_in[2];
    const float* w_scale = (const float*)d_in[3];
    const float* b_scale = (const float*)d_in[4];
    const float* w_om    = (const float*)d_in[5];
    const float* b_om    = (const float*)d_in[6];
    const float* w_proj  = (const float*)d_in[7];
    const float* b_proj  = (const float*)d_in[8];
    const float* ln_g    = (const float*)d_in[9];
    const float* ln_b    = (const float*)d_in[10];
    const float* wa1 = (const float*)d_in[11];
    const float* ba1 = (const float*)d_in[12];
    const float* wb1 = (const float*)d_in[13];
    const float* bb1 = (const float*)d_in[14];
    const float* wa2 = (const float*)d_in[15];
    const float* ba2 = (const float*)d_in[16];
    const float* wb2 = (const float*)d_in[17];
    const float* bb2 = (const float*)d_in[18];
    float* out = (float*)d_out;

    k_wprep<<<((OMC/2)*CC*9 + 255)/256, 256>>>(w_om);
    k_pool<<<dim3(CC, NB, 3), 256>>>(f1, f2, f3);
    k_scale_gemv<<<(3*NB*CC*32 + 255)/256, 256>>>(w_scale, b_scale);
    k_apply<<<dim3(168, CC/32, NB), dim3(32, 8)>>>(f1, f2, f3);
    k_conv3x3<<<dim3(1, 1, 864), 256>>>();
    k_omred<<<1134, 256>>>(b_om);
    k_dcn<<<dim3(672, GG, NB), 256>>>();
    k_proj<<<dim3(NB*TP/128, CC/64), 256>>>(w_proj, b_proj);
    k_lngate<<<NB*TP/8, 256>>>(ln_g, ln_b);
    k_pool2a<<<dim3(84, NB), 256>>>();
    k_pool2b<<<dim3(3, NB), 256>>>();
    k_task_gemv<<<(4*3*NB*CC*32 + 255)/256, 256>>>(wa1, ba1, wb1, bb1, wa2, ba2, wb2, bb2);
    k_taskout<<<dim3(168, CC/32, NB), dim3(32, 8)>>>(out);
}

// round 6
// speedup vs baseline: 4.2297x; 1.0539x over previous
#include <cuda_runtime.h>
#include <math.h>

#define CC    256
#define GG    4
#define NB    2
#define OMC   108          // G*K*3
#define TP    5376         // total pixels per batch across scales (4096+1024+256)
#define OCB   12           // out-channels per conv block (6 pairs)
#define OCP   6            // oc-pairs per conv block
#define NOCB  9            // 108 / 12
#define CB    8            // channels per conv inner batch

// per-scale facts (s = 0,1,2): H=W=64>>s, HW=4096>>(2s), SOFF={0,4096,5120}, CS={2,8,16}
#define SEL3(s,a,b,c) ((s)==0 ? (a) : ((s)==1 ? (b) : (c)))

typedef unsigned long long ull;

__device__ __forceinline__ ull f2pk(float lo, float hi) {
    ull r; asm("mov.b64 %0, {%1, %2};" : "=l"(r) : "f"(lo), "f"(hi)); return r;
}
__device__ __forceinline__ void f2fma(ull &d, ull a, ull b) {
    asm("fma.rn.f32x2 %0, %1, %2, %0;" : "+l"(d) : "l"(a), "l"(b));
}
__device__ __forceinline__ float2 f2up(ull v) {
    float2 o; asm("mov.b64 {%0, %1}, %2;" : "=f"(o.x), "=f"(o.y) : "l"(v)); return o;
}

// ---------------- scratch (static device globals) ---------------------------
__device__ float g_xt [NB*TP*CC];        // scaled input, pixel-major [b][p][c]
__device__ float g_om [NB*OMC*TP];       // offset/mask conv output (per-scale blocks)
__device__ float g_omp[6193152];         // conv partials (channel split, all scales)
__device__ float g_dcn[NB*TP*CC];        // dcn gather output [row][c]
__device__ float g_d  [NB*TP*CC];        // proj output       [row][c]
__device__ float g_x2t[NB*TP*CC];        // after spatial gate [row][c]
__device__ ull   g_wp [(OMC/2)*CC*9];    // conv weights packed {w_oc, w_oc+1}
__device__ float g_pool [3*NB*CC];
__device__ float g_sfac [3*NB*CC];
__device__ float g_part [NB*84*CC];
__device__ float g_pool2[3*NB*CC];
__device__ float g_ab  [4*3*NB*CC];      // [which][s][b][c]

#define OMOFF(s) SEL3(s, 0, 884736, 1105920)
#define POFF(s)  SEL3(s, 0, 3538944, 5308416)

// ---------------- weight pair-pack prep --------------------------------------
__global__ __launch_bounds__(256) void k_wprep(const float* __restrict__ wom) {
    int i = blockIdx.x*256 + threadIdx.x;
    if (i < (OMC/2)*CC*9) {
        int op = i / (CC*9), rem = i % (CC*9);
        g_wp[i] = f2pk(wom[(size_t)(2*op)*CC*9 + rem], wom[(size_t)(2*op+1)*CC*9 + rem]);
    }
}

// ---------------- stage A: channel scale attention (all scales) --------------
__global__ __launch_bounds__(256) void k_pool(const float* __restrict__ f1,
                                              const float* __restrict__ f2,
                                              const float* __restrict__ f3) {
    int c = blockIdx.x, b = blockIdx.y, s = blockIdx.z;
    int HW = 4096 >> (2*s);
    const float* x = SEL3(s, f1, f2, f3);
    const float* p = x + ((size_t)b*CC + c)*HW;
    float v = 0.f;
    for (int i = threadIdx.x; i < HW; i += 256) v += p[i];
    __shared__ float sm[8];
    int lane = threadIdx.x & 31, wid = threadIdx.x >> 5;
#pragma unroll
    for (int o = 16; o; o >>= 1) v += __shfl_down_sync(0xffffffffu, v, o);
    if (!lane) sm[wid] = v;
    __syncthreads();
    if (threadIdx.x == 0) {
        float t = 0.f;
#pragma unroll
        for (int i = 0; i < 8; i++) t += sm[i];
        g_pool[(s*NB + b)*CC + c] = t / (float)HW;
    }
}

__global__ __launch_bounds__(256) void k_scale_gemv(const float* __restrict__ wsc,
                                                    const float* __restrict__ bsc) {
    int gw = (blockIdx.x*blockDim.x + threadIdx.x) >> 5;
    int lane = threadIdx.x & 31;
    if (gw >= 3*NB*CC) return;
    int sb = gw / CC, o = gw % CC;       // sb = s*NB + b
    const float* wr = wsc + (size_t)o*CC;
    const float* pr = g_pool + sb*CC;
    float v = 0.f;
#pragma unroll
    for (int i = 0; i < CC/32; i++) v = fmaf(wr[lane + i*32], pr[lane + i*32], v);
#pragma unroll
    for (int o2 = 16; o2; o2 >>= 1) v += __shfl_down_sync(0xffffffffu, v, o2);
    if (!lane) {
        v = (v + bsc[o] + 1.f) * 0.5f;
        g_sfac[sb*CC + o] = fminf(fmaxf(v, 0.f), 1.f);
    }
}

// scale + transpose to pixel-major (all scales; x-tile cum {128,160,168})
__global__ __launch_bounds__(256) void k_apply(const float* __restrict__ f1,
                                               const float* __restrict__ f2,
                                               const float* __restrict__ f3) {
    __shared__ float t[32][33];
    int bx = blockIdx.x;
    int s = (bx >= 128) + (bx >= 160);
    int base = SEL3(s, 0, 128, 160);
    int HW = 4096 >> (2*s);
    int SOFF = SEL3(s, 0, 4096, 5120);
    const float* x = SEL3(s, f1, f2, f3);
    int b = blockIdx.z;
    int hw0 = (bx - base)*32, c0 = blockIdx.y*32;
    int tx = threadIdx.x, ty = threadIdx.y;     // 32 x 8
#pragma unroll
    for (int i = 0; i < 4; i++) {
        int c = c0 + ty + i*8;
        t[ty + i*8][tx] = x[((size_t)b*CC + c)*HW + hw0 + tx] * g_sfac[(s*NB + b)*CC + c];
    }
    __syncthreads();
#pragma unroll
    for (int i = 0; i < 4; i++) {
        int hw = hw0 + ty + i*8;
        g_xt[((size_t)b*TP + SOFF + hw)*CC + c0 + tx] = t[tx][ty + i*8];
    }
}

// ---------------- 3x3 conv producing offsets/masks (all scales) --------------
// 288 blocks per scale, grid.z = 864; CB=8 channels per inner batch
__global__ __launch_bounds__(256,2) void k_conv3x3() {
    int z = blockIdx.z;
    int s = z / 288;
    int r = z % 288;
    int CS = SEL3(s, 2, 8, 16);
    int H = 64 >> s, W = 64 >> s, HW = H*W;
    int SOFF = SEL3(s, 0, 4096, 5120);
    int nx = SEL3(s, 2, 1, 1);

    int cs = r % CS;  r /= CS;
    int ocb = r % NOCB; r /= NOCB;
    int b = r % NB;   r /= NB;
    int txi = r % nx, tyi = r / nx;
    int tx0 = txi*32, ty0 = tyi*16;
    int cbase = cs * (CC/CS), cend = cbase + CC/CS;

    __shared__ float sIn[CB][18*35];
    __shared__ ull sW[OCP][CB*9];

    int tid = threadIdx.x;
    int tx = tid & 31, ty = tid >> 5;          // ty in 0..7
    ull a0[OCP], a1[OCP];
#pragma unroll
    for (int i = 0; i < OCP; i++) { a0[i] = 0ull; a1[i] = 0ull; }

    const float* xb = g_xt + ((size_t)b*TP + SOFF)*CC;

    for (int c0 = cbase; c0 < cend; c0 += CB) {
        __syncthreads();
        // halo 18x34, 8 channels at once via 2x float4 from pixel-major g_xt
        for (int i = tid; i < 18*34; i += 256) {
            int rr = i / 34, cl = i - rr*34;
            int gh = ty0 + rr - 1, gw = tx0 + cl - 1;
            float4 v0 = make_float4(0.f, 0.f, 0.f, 0.f);
            float4 v1 = make_float4(0.f, 0.f, 0.f, 0.f);
            if ((unsigned)gh < (unsigned)H && (unsigned)gw < (unsigned)W) {
                const float* px = xb + (size_t)(gh*W + gw)*CC + c0;
                v0 = *(const float4*)px;
                v1 = *(const float4*)(px + 4);
            }
            int o = rr*35 + cl;
            sIn[0][o] = v0.x; sIn[1][o] = v0.y; sIn[2][o] = v0.z; sIn[3][o] = v0.w;
            sIn[4][o] = v1.x; sIn[5][o] = v1.y; sIn[6][o] = v1.z; sIn[7][o] = v1.w;
        }
        // packed weights: OCP x CB x 9 (ull each)
        for (int i = tid; i < OCP*CB*9; i += 256) {
            int p = i / (CB*9);
            int rem = i - p*(CB*9);
            sW[p][rem] = g_wp[((size_t)(ocb*OCP + p)*CC + c0 + rem/9)*9 + rem%9];
        }
        __syncthreads();

#pragma unroll
        for (int ch = 0; ch < CB; ch++) {
#pragma unroll
            for (int t = 0; t < 9; t++) {
                int dy = t/3, dx = t%3;
                int bse = (ty + dy)*35 + tx + dx;
                float v0 = sIn[ch][bse];
                float v1 = sIn[ch][bse + 8*35];
                ull i0 = f2pk(v0, v0);
                ull i1 = f2pk(v1, v1);
#pragma unroll
                for (int p = 0; p < OCP; p++) {
                    ull w = sW[p][ch*9 + t];
                    f2fma(a0[p], w, i0);
                    f2fma(a1[p], w, i1);
                }
            }
        }
    }
    int h0 = ty0 + ty, w0 = tx0 + tx;
    size_t pbase = (size_t)POFF(s) + ((size_t)cs*NB + b)*(size_t)OMC*HW;
    if (w0 < W) {
#pragma unroll
        for (int p = 0; p < OCP; p++) {
            int oc = ocb*OCB + 2*p;
            float2 v = f2up(a0[p]);
            float2 u = f2up(a1[p]);
            if (h0 < H) {
                g_omp[pbase + (size_t)(oc  )*HW + h0*W + w0] = v.x;
                g_omp[pbase + (size_t)(oc+1)*HW + h0*W + w0] = v.y;
            }
            if (h0 + 8 < H) {
                g_omp[pbase + (size_t)(oc  )*HW + (h0+8)*W + w0] = u.x;
                g_omp[pbase + (size_t)(oc+1)*HW + (h0+8)*W + w0] = u.y;
            }
        }
    }
}

// reduce channel-split partials + bias (float4); x-cum {864,1080,1134}
__global__ __launch_bounds__(256) void k_omred(const float* __restrict__ bom) {
    int bx = blockIdx.x;
    int s = (bx >= 864) + (bx >= 1080);
    int base = SEL3(s, 0, 864, 1080);
    int CS = SEL3(s, 2, 8, 16);
    int HW = 4096 >> (2*s);
    int e = ((bx - base)*256 + threadIdx.x)*4;
    int b  = e / (OMC*HW);
    int rem = e - b*OMC*HW;
    int oc = rem / HW;
    float bia = bom[oc];
    float4 v = make_float4(bia, bia, bia, bia);
    size_t pb = (size_t)POFF(s);
    for (int cs = 0; cs < CS; cs++) {
        float4 p = *(const float4*)(g_omp + pb + ((size_t)cs*NB + b)*(size_t)OMC*HW + rem);
        v.x += p.x; v.y += p.y; v.z += p.z; v.w += p.w;
    }
    *(float4*)(g_om + OMOFF(s) + (size_t)e) = v;
}

// ---------------- DCNv4 bilinear gather (branchless corners) -----------------
__global__ __launch_bounds__(256) void k_dcn() {
    int bx = blockIdx.x;
    int s = (bx >= 512) + (bx >= 640);
    int base = SEL3(s, 0, 512, 640);
    int H = 64 >> s, W = 64 >> s, HW = H*W;
    int SOFF = SEL3(s, 0, 4096, 5120);
    int warp = threadIdx.x >> 5, lane = threadIdx.x & 31;
    int hw = (bx - base)*8 + warp;
    int g = blockIdx.y, b = blockIdx.z;
    int h = hw / W, w = hw % W;
    const float* omb = g_om + OMOFF(s) + (size_t)b*OMC*HW;
    const float* xb  = g_xt + ((size_t)b*TP + SOFF)*CC + g*64;
    ull acc = 0ull;
#pragma unroll
    for (int k = 0; k < 9; k++) {
        int ky = k/3 - 1, kx = k%3 - 1;
        int ch = (g*9 + k)*3;
        float offy = omb[(size_t)(ch+0)*HW + hw];
        float offx = omb[(size_t)(ch+1)*HW + hw];
        float msk  = omb[(size_t)(ch+2)*HW + hw];
        float py = (float)(h + ky) + offy;
        float px = (float)(w + kx) + offx;
        float y0f = floorf(py), x0f = floorf(px);
        float fy = py - y0f, fx = px - x0f;
        int y0 = (int)y0f, x0 = (int)x0f;
#pragma unroll
        for (int t = 0; t < 4; t++) {
            int dy = t >> 1, dx = t & 1;
            int yy = y0 + dy, xx = x0 + dx;
            float wgt = (dy ? fy : 1.f - fy) * (dx ? fx : 1.f - fx);
            bool valid = (yy >= 0) && (yy < H) && (xx >= 0) && (xx < W);
            float weff = valid ? wgt * msk : 0.f;
            int yc = min(max(yy, 0), H-1);
            int xc = min(max(xx, 0), W-1);
            const ull* p = (const ull*)(xb + (size_t)(yc*W + xc)*CC);
            f2fma(acc, f2pk(weff, weff), p[lane]);
        }
    }
    ((ull*)(g_dcn + ((size_t)b*TP + SOFF + hw)*CC + g*64))[lane] = acc;
}

// ---------------- 1x1 projection GEMM (f32x2); M = NB*TP = 10752 -------------
__global__ __launch_bounds__(256,2) void k_proj(const float* __restrict__ wp,
                                                const float* __restrict__ bp) {
    __shared__ float As[16][128];
    __shared__ ull   Bs2[16][64];
    int tid = threadIdx.x;
    int m0 = blockIdx.x*128, n0 = blockIdx.y*64;
    ull acc[4][4];
#pragma unroll
    for (int i = 0; i < 4; i++)
#pragma unroll
        for (int j = 0; j < 4; j++) acc[i][j] = 0ull;
    int lm = tid >> 1, lkq = (tid & 1)*8;
    int ln = tid >> 2, lk4 = (tid & 3)*4;
    int tm = tid >> 4, tn = tid & 15;
    for (int k0 = 0; k0 < CC; k0 += 16) {
        float4 aq0 = *(const float4*)(g_dcn + (size_t)(m0+lm)*CC + k0 + lkq);
        float4 aq1 = *(const float4*)(g_dcn + (size_t)(m0+lm)*CC + k0 + lkq + 4);
        float4 bv = *(const float4*)(wp    + (size_t)(n0+ln)*CC + k0 + lk4);
        __syncthreads();
        As[lkq+0][lm] = aq0.x; As[lkq+1][lm] = aq0.y; As[lkq+2][lm] = aq0.z; As[lkq+3][lm] = aq0.w;
        As[lkq+4][lm] = aq1.x; As[lkq+5][lm] = aq1.y; As[lkq+6][lm] = aq1.z; As[lkq+7][lm] = aq1.w;
        Bs2[lk4+0][ln] = f2pk(bv.x, bv.x);
        Bs2[lk4+1][ln] = f2pk(bv.y, bv.y);
        Bs2[lk4+2][ln] = f2pk(bv.z, bv.z);
        Bs2[lk4+3][ln] = f2pk(bv.w, bv.w);
        __syncthreads();
#pragma unroll
        for (int kk = 0; kk < 16; kk++) {
            ull ra[4], rb[4];
#pragma unroll
            for (int i = 0; i < 4; i++) ra[i] = *(const ull*)&As[kk][2*tm + 32*i];
#pragma unroll
            for (int j = 0; j < 4; j++) rb[j] = Bs2[kk][tn + 16*j];
#pragma unroll
            for (int i = 0; i < 4; i++)
#pragma unroll
                for (int j = 0; j < 4; j++) f2fma(acc[i][j], ra[i], rb[j]);
        }
    }
#pragma unroll
    for (int i = 0; i < 4; i++)
#pragma unroll
        for (int j = 0; j < 4; j++) {
            float2 v = f2up(acc[i][j]);
            int mm = m0 + 2*tm + 32*i, nn = n0 + tn + 16*j;
            float bia = bp[nn];
            g_d[(size_t)mm*CC + nn]     = v.x + bia;
            g_d[(size_t)(mm+1)*CC + nn] = v.y + bia;
        }
}

// ---------------- channel LayerNorm + sigmoid gate (warp per row) ------------
__global__ __launch_bounds__(256) void k_lngate(const float* __restrict__ lng,
                                                const float* __restrict__ lnb) {
    int warp = threadIdx.x >> 5, lane = threadIdx.x & 31;
    int r = blockIdx.x*8 + warp;
    size_t base = (size_t)r*CC;
    float4 v0 = *(const float4*)(g_d + base + lane*8);
    float4 v1 = *(const float4*)(g_d + base + lane*8 + 4);
    float s = v0.x+v0.y+v0.z+v0.w + v1.x+v1.y+v1.z+v1.w;
    float q = v0.x*v0.x+v0.y*v0.y+v0.z*v0.z+v0.w*v0.w
            + v1.x*v1.x+v1.y*v1.y+v1.z*v1.z+v1.w*v1.w;
#pragma unroll
    for (int o = 16; o; o >>= 1) {
        s += __shfl_xor_sync(0xffffffffu, s, o);
        q += __shfl_xor_sync(0xffffffffu, q, o);
    }
    float mu = s * (1.f/CC);
    float rs = rsqrtf(q * (1.f/CC) - mu*mu + 1e-5f);
    float4 g0 = *(const float4*)(lng + lane*8);
    float4 g1 = *(const float4*)(lng + lane*8 + 4);
    float4 b0 = *(const float4*)(lnb + lane*8);
    float4 b1 = *(const float4*)(lnb + lane*8 + 4);
    float4 x0 = *(const float4*)(g_xt + base + lane*8);
    float4 x1 = *(const float4*)(g_xt + base + lane*8 + 4);
    float4 o0, o1;
    o0.x = x0.x / (1.f + expf(-((v0.x-mu)*rs*g0.x + b0.x)));
    o0.y = x0.y / (1.f + expf(-((v0.y-mu)*rs*g0.y + b0.y)));
    o0.z = x0.z / (1.f + expf(-((v0.z-mu)*rs*g0.z + b0.z)));
    o0.w = x0.w / (1.f + expf(-((v0.w-mu)*rs*g0.w + b0.w)));
    o1.x = x1.x / (1.f + expf(-((v1.x-mu)*rs*g1.x + b1.x)));
    o1.y = x1.y / (1.f + expf(-((v1.y-mu)*rs*g1.y + b1.y)));
    o1.z = x1.z / (1.f + expf(-((v1.z-mu)*rs*g1.z + b1.z)));
    o1.w = x1.w / (1.f + expf(-((v1.w-mu)*rs*g1.w + b1.w)));
    *(float4*)(g_x2t + base + lane*8)     = o0;
    *(float4*)(g_x2t + base + lane*8 + 4) = o1;
}

// ---------------- task attention: pooled mean (64-row slabs; cum {64,80,84}) --
__global__ __launch_bounds__(256) void k_pool2a() {
    int slab = blockIdx.x, b = blockIdx.y;
    int s = (slab >= 64) + (slab >= 80);
    int sbase = SEL3(s, 0, 64, 80);
    int SOFF = SEL3(s, 0, 4096, 5120);
    int c = threadIdx.x;
    int r0 = SOFF + (slab - sbase)*64;
    float v = 0.f;
    for (int r = r0; r < r0 + 64; r++)
        v += g_x2t[((size_t)b*TP + r)*CC + c];
    g_part[(b*84 + slab)*CC + c] = v;
}

__global__ __launch_bounds__(256) void k_pool2b() {
    int s = blockIdx.x, b = blockIdx.y, c = threadIdx.x;
    int slabs = SEL3(s, 64, 16, 4);
    int sbase = SEL3(s, 0, 64, 80);
    int HW = 4096 >> (2*s);
    float v = 0.f;
    for (int i = 0; i < slabs; i++) v += g_part[(b*84 + sbase + i)*CC + c];
    g_pool2[(s*NB + b)*CC + c] = v / (float)HW;
}

__global__ __launch_bounds__(256) void k_task_gemv(
        const float* __restrict__ wa1, const float* __restrict__ ba1,
        const float* __restrict__ wb1, const float* __restrict__ bb1,
        const float* __restrict__ wa2, const float* __restrict__ ba2,
        const float* __restrict__ wb2, const float* __restrict__ bb2) {
    int gw = (blockIdx.x*blockDim.x + threadIdx.x) >> 5;
    int lane = threadIdx.x & 31;
    if (gw >= 4*3*NB*CC) return;
    int which = gw / (3*NB*CC);
    int rem = gw % (3*NB*CC);
    int sb = rem / CC, o = rem % CC;     // sb = s*NB + b
    const float* ws = (which == 0) ? wa1 : (which == 1) ? wb1 : (which == 2) ? wa2 : wb2;
    const float* bs = (which == 0) ? ba1 : (which == 1) ? bb1 : (which == 2) ? ba2 : bb2;
    const float* wr = ws + (size_t)o*CC;
    const float* pr = g_pool2 + sb*CC;
    float v = 0.f;
#pragma unroll
    for (int i = 0; i < CC/32; i++) v = fmaf(wr[lane + i*32], pr[lane + i*32], v);
#pragma unroll
    for (int o2 = 16; o2; o2 >>= 1) v += __shfl_down_sync(0xffffffffu, v, o2);
    if (!lane) g_ab[(which*3*NB + sb)*CC + o] = fmaxf(v + bs[o], 0.f);
}

// gated output + transpose back to per-scale [b][c][hw]; x-cum {128,160,168}
__global__ __launch_bounds__(256) void k_taskout(float* __restrict__ out) {
    __shared__ float t[32][33];
    int bx = blockIdx.x;
    int s = (bx >= 128) + (bx >= 160);
    int base = SEL3(s, 0, 128, 160);
    int HW = 4096 >> (2*s);
    int SOFF = SEL3(s, 0, 4096, 5120);
    size_t OOFF = (size_t)NB*CC*SOFF;
    int b = blockIdx.z;
    int hw0 = (bx - base)*32, c0 = blockIdx.y*32;
    int tx = threadIdx.x, ty = threadIdx.y;   // 32 x 8
    int sb = s*NB + b;
#pragma unroll
    for (int i = 0; i < 4; i++) {
        int hw = hw0 + ty + i*8, c = c0 + tx;
        float v  = g_x2t[((size_t)b*TP + SOFF + hw)*CC + c];
        float A1 = g_ab[(0*3*NB + sb)*CC + c];
        float B1 = g_ab[(1*3*NB + sb)*CC + c];
        float A2 = g_ab[(2*3*NB + sb)*CC + c];
        float B2 = g_ab[(3*3*NB + sb)*CC + c];
        t[tx][ty + i*8] = fmaxf(fmaf(A1, v, B1), fmaf(A2, v, B2));
    }
    __syncthreads();
#pragma unroll
    for (int i = 0; i < 4; i++) {
        int c = c0 + ty + i*8, hw = hw0 + tx;
        out[OOFF + ((size_t)b*CC + c)*HW + hw] = t[ty + i*8][tx];
    }
}

// ---------------- launch ------------------------------------------------------
extern "C" void kernel_launch(void* const* d_in, const int* in_sizes, int n_in,
                              void* d_out, int out_size) {
    const float* f1 = (const float*)d_in[0];
    const float* f2 = (const float*)d_in[1];
    const float* f3 = (const float*)d_in[2];
    const float* w_scale = (const float*)d_in[3];
    const float* b_scale = (const float*)d_in[4];
    const float* w_om    = (const float*)d_in[5];
    const float* b_om    = (const float*)d_in[6];
    const float* w_proj  = (const float*)d_in[7];
    const float* b_proj  = (const float*)d_in[8];
    const float* ln_g    = (const float*)d_in[9];
    const float* ln_b    = (const float*)d_in[10];
    const float* wa1 = (const float*)d_in[11];
    const float* ba1 = (const float*)d_in[12];
    const float* wb1 = (const float*)d_in[13];
    const float* bb1 = (const float*)d_in[14];
    const float* wa2 = (const float*)d_in[15];
    const float* ba2 = (const float*)d_in[16];
    const float* wb2 = (const float*)d_in[17];
    const float* bb2 = (const float*)d_in[18];
    float* out = (float*)d_out;

    k_wprep<<<((OMC/2)*CC*9 + 255)/256, 256>>>(w_om);
    k_pool<<<dim3(CC, NB, 3), 256>>>(f1, f2, f3);
    k_scale_gemv<<<(3*NB*CC*32 + 255)/256, 256>>>(w_scale, b_scale);
    k_apply<<<dim3(168, CC/32, NB), dim3(32, 8)>>>(f1, f2, f3);
    k_conv3x3<<<dim3(1, 1, 864), 256>>>();
    k_omred<<<1134, 256>>>(b_om);
    k_dcn<<<dim3(672, GG, NB), 256>>>();
    k_proj<<<dim3(NB*TP/128, CC/64), 256>>>(w_proj, b_proj);
    k_lngate<<<NB*TP/8, 256>>>(ln_g, ln_b);
    k_pool2a<<<dim3(84, NB), 256>>>();
    k_pool2b<<<dim3(3, NB), 256>>>();
    k_task_gemv<<<(4*3*NB*CC*32 + 255)/256, 256>>>(wa1, ba1, wb1, bb1, wa2, ba2, wb2, bb2);
    k_taskout<<<dim3(168, CC/32, NB), dim3(32, 8)>>>(out);
}

// round 8
// speedup vs baseline: 5.4462x; 1.2876x over previous
#include <cuda_runtime.h>
#include <math.h>
#include <stdint.h>

#define CC    256
#define GG    4
#define NB    2
#define OMC   108          // G*K*3
#define TP    5376         // total pixels per batch across scales (4096+1024+256)
#define SEL3(s,a,b,c) ((s)==0 ? (a) : ((s)==1 ? (b) : (c)))

typedef unsigned long long ull;

__device__ __forceinline__ ull f2pk(float lo, float hi) {
    ull r; asm("mov.b64 %0, {%1, %2};" : "=l"(r) : "f"(lo), "f"(hi)); return r;
}
__device__ __forceinline__ void f2fma(ull &d, ull a, ull b) {
    asm("fma.rn.f32x2 %0, %1, %2, %0;" : "+l"(d) : "l"(a), "l"(b));
}
__device__ __forceinline__ float2 f2up(ull v) {
    float2 o; asm("mov.b64 {%0, %1}, %2;" : "=f"(o.x), "=f"(o.y) : "l"(v)); return o;
}
__device__ __forceinline__ float tf32r(float x) {
    float r; asm("cvt.rna.tf32.f32 %0, %1;" : "=f"(r) : "f"(x)); return r;
}

// warp-level tf32 MMA (sm_80+ path; compiles on plain sm_103)
#define MMA8(d, a, b0, b1) \
    asm volatile("mma.sync.aligned.m16n8k8.row.col.f32.tf32.tf32.f32 " \
        "{%0,%1,%2,%3}, {%4,%5,%6,%7}, {%8,%9}, {%0,%1,%2,%3};" \
        : "+f"((d)[0]), "+f"((d)[1]), "+f"((d)[2]), "+f"((d)[3]) \
        : "r"((a)[0]), "r"((a)[1]), "r"((a)[2]), "r"((a)[3]), "r"(b0), "r"(b1))

// ---------------- scratch (static device globals) ---------------------------
__device__ float g_xt [NB*TP*CC];        // scaled input, pixel-major [b][p][c]
__device__ float g_om [NB*OMC*TP];       // offset/mask conv output (per-scale blocks)
__device__ float g_dcn[NB*TP*CC];
__device__ float g_d  [NB*TP*CC];
__device__ float g_x2t[NB*TP*CC];
__device__ float g_wt [72*32*112];       // conv weights tf32: [tap*8+ck][kk(32)][n(112)]
__device__ float g_pool [3*NB*CC];
__device__ float g_sfac [3*NB*CC];
__device__ float g_part [NB*84*CC];
__device__ float g_pool2[3*NB*CC];
__device__ float g_ab  [4*3*NB*CC];

#define OMOFF(s) SEL3(s, 0, 884736, 1105920)

// ---------------- weight prep: w_om -> tf32 tiles [i][kk][n] ------------------
__global__ __launch_bounds__(256) void k_wprep2(const float* __restrict__ wom) {
    int idx = blockIdx.x*256 + threadIdx.x;
    if (idx >= 72*3584) return;
    int i = idx / 3584, r = idx % 3584, kk = r / 112, n = r % 112;
    int t = i >> 3, ck = i & 7, c = ck*32 + kk;
    float v = (n < OMC) ? wom[n*2304 + c*9 + t] : 0.f;
    g_wt[idx] = tf32r(v);
}

// ---------------- stage A: channel scale attention ---------------------------
__global__ __launch_bounds__(256) void k_pool(const float* __restrict__ f1,
                                              const float* __restrict__ f2,
                                              const float* __restrict__ f3) {
    int c = blockIdx.x, b = blockIdx.y, s = blockIdx.z;
    int HW = 4096 >> (2*s);
    const float* x = SEL3(s, f1, f2, f3);
    const float* p = x + ((size_t)b*CC + c)*HW;
    float v = 0.f;
    for (int i = threadIdx.x; i < HW; i += 256) v += p[i];
    __shared__ float sm[8];
    int lane = threadIdx.x & 31, wid = threadIdx.x >> 5;
#pragma unroll
    for (int o = 16; o; o >>= 1) v += __shfl_down_sync(0xffffffffu, v, o);
    if (!lane) sm[wid] = v;
    __syncthreads();
    if (threadIdx.x == 0) {
        float t = 0.f;
#pragma unroll
        for (int i = 0; i < 8; i++) t += sm[i];
        g_pool[(s*NB + b)*CC + c] = t / (float)HW;
    }
}

__global__ __launch_bounds__(256) void k_scale_gemv(const float* __restrict__ wsc,
                                                    const float* __restrict__ bsc) {
    int gw = (blockIdx.x*blockDim.x + threadIdx.x) >> 5;
    int lane = threadIdx.x & 31;
    if (gw >= 3*NB*CC) return;
    int sb = gw / CC, o = gw % CC;
    const float* wr = wsc + (size_t)o*CC;
    const float* pr = g_pool + sb*CC;
    float v = 0.f;
#pragma unroll
    for (int i = 0; i < CC/32; i++) v = fmaf(wr[lane + i*32], pr[lane + i*32], v);
#pragma unroll
    for (int o2 = 16; o2; o2 >>= 1) v += __shfl_down_sync(0xffffffffu, v, o2);
    if (!lane) {
        v = (v + bsc[o] + 1.f) * 0.5f;
        g_sfac[sb*CC + o] = fminf(fmaxf(v, 0.f), 1.f);
    }
}

__global__ __launch_bounds__(256) void k_apply(const float* __restrict__ f1,
                                               const float* __restrict__ f2,
                                               const float* __restrict__ f3) {
    __shared__ float t[32][33];
    int bx = blockIdx.x;
    int s = (bx >= 128) + (bx >= 160);
    int base = SEL3(s, 0, 128, 160);
    int HW = 4096 >> (2*s);
    int SOFF = SEL3(s, 0, 4096, 5120);
    const float* x = SEL3(s, f1, f2, f3);
    int b = blockIdx.z;
    int hw0 = (bx - base)*32, c0 = blockIdx.y*32;
    int tx = threadIdx.x, ty = threadIdx.y;
#pragma unroll
    for (int i = 0; i < 4; i++) {
        int c = c0 + ty + i*8;
        t[ty + i*8][tx] = x[((size_t)b*CC + c)*HW + hw0 + tx] * g_sfac[(s*NB + b)*CC + c];
    }
    __syncthreads();
#pragma unroll
    for (int i = 0; i < 4; i++) {
        int hw = hw0 + ty + i*8;
        g_xt[((size_t)b*TP + SOFF + hw)*CC + c0 + tx] = t[tx][ty + i*8];
    }
}

// ---------------- 3x3 conv via mma.sync tf32 implicit GEMM -------------------
// CTA: 128 padded pixels x 112 oc; K = 9 taps x 256 ch = 72 iters of 32
__global__ __launch_bounds__(256) void k_convmma(const float* __restrict__ bom) {
    __shared__ float As[128*36];     // A tile, stride 36 (conflict-free frags)
    __shared__ float Bs[32*120];     // B tile [kk][n], stride 120

    int tid = threadIdx.x, wid = tid >> 5, lane = tid & 31;
    int x = blockIdx.x;
    int s = (x >= 70) + (x >= 90);
    int r = x - SEL3(s, 0, 70, 90);
    int TILES = SEL3(s, 35, 10, 3);
    int b = r / TILES, tile = r % TILES;
    int H = 64 >> s, W = H, HW = H*W, W2 = W + 2, PPn = (H+2)*(W+2);
    int SOFF = SEL3(s, 0, 4096, 5120);
    int p0 = tile*128;
    const float* xb = g_xt + ((size_t)b*TP + SOFF)*CC;

    // per-thread fill metadata
    int q = tid & 7;
    int pyb[4], pxb[4], rowk[4];
    bool ppok[4];
    int bkk[4], bnq[4];
    bool bok[4];
#pragma unroll
    for (int k = 0; k < 4; k++) {
        rowk[k] = (tid >> 3) + 32*k;
        int pp = p0 + rowk[k];
        ppok[k] = pp < PPn;
        pyb[k] = pp / W2 - 1;
        pxb[k] = pp % W2 - 1;
        int u = tid + 256*k;
        bok[k] = u < 896;
        bkk[k] = u / 28;
        bnq[k] = u % 28;
    }

    float4 rA[4], rB[4];
#define LOADI(i) do {                                                            \
    int _t = (i) >> 3, _ck = (i) & 7;                                            \
    int _dy = _t/3 - 1, _dx = _t%3 - 1;                                          \
    _Pragma("unroll")                                                            \
    for (int k = 0; k < 4; k++) {                                                \
        int _py = pyb[k] + _dy, _px = pxb[k] + _dx;                              \
        bool _v = ppok[k] && (unsigned)_py < (unsigned)H && (unsigned)_px < (unsigned)W; \
        float4 _val = make_float4(0.f, 0.f, 0.f, 0.f);                           \
        if (_v) _val = *(const float4*)(xb + (size_t)(_py*W + _px)*CC + _ck*32 + q*4); \
        rA[k] = _val;                                                            \
        float4 _bv = make_float4(0.f, 0.f, 0.f, 0.f);                            \
        if (bok[k]) _bv = *(const float4*)(g_wt + (size_t)(i)*3584 + bkk[k]*112 + bnq[k]*4); \
        rB[k] = _bv;                                                             \
    }                                                                            \
} while (0)

    float d[2][7][4];
#pragma unroll
    for (int mi = 0; mi < 2; mi++)
#pragma unroll
        for (int ni = 0; ni < 7; ni++)
#pragma unroll
            for (int e = 0; e < 4; e++) d[mi][ni][e] = 0.f;

    int wm = wid & 3, wn = wid >> 2;        // 4 M-warps x 2 N-warps
    int lr = lane >> 2, kc = lane & 3;
    const uint32_t* A32 = (const uint32_t*)As;
    const uint32_t* B32 = (const uint32_t*)Bs;

    LOADI(0);
    for (int i = 0; i < 72; i++) {
        if (i > 0) __syncthreads();          // prev compute done before overwrite
#pragma unroll
        for (int k = 0; k < 4; k++) {
            float4 v = rA[k];
            v.x = tf32r(v.x); v.y = tf32r(v.y); v.z = tf32r(v.z); v.w = tf32r(v.w);
            *(float4*)(As + rowk[k]*36 + q*4) = v;
            if (bok[k]) *(float4*)(Bs + bkk[k]*120 + bnq[k]*4) = rB[k];
        }
        if (i + 1 < 72) LOADI(i + 1);        // issue next LDGs before compute
        __syncthreads();

#pragma unroll
        for (int kq = 0; kq < 32; kq += 8) {
            uint32_t a[2][4];
#pragma unroll
            for (int mi = 0; mi < 2; mi++) {
                int rr = wm*32 + mi*16 + lr;
                a[mi][0] = A32[rr*36 + kq + kc];
                a[mi][1] = A32[(rr+8)*36 + kq + kc];
                a[mi][2] = A32[rr*36 + kq + kc + 4];
                a[mi][3] = A32[(rr+8)*36 + kq + kc + 4];
            }
#pragma unroll
            for (int ni = 0; ni < 7; ni++) {
                int nn = wn*56 + ni*8 + lr;
                uint32_t b0 = B32[(kq+kc)*120 + nn];
                uint32_t b1 = B32[(kq+kc+4)*120 + nn];
                MMA8(d[0][ni], a[0], b0, b1);
                MMA8(d[1][ni], a[1], b0, b1);
            }
        }
    }

    // epilogue: scatter to g_om (channel-major) + bias
    float* obase = g_om + OMOFF(s) + (size_t)b*OMC*HW;
#pragma unroll
    for (int mi = 0; mi < 2; mi++) {
#pragma unroll
        for (int h = 0; h < 2; h++) {
            int pp = p0 + wm*32 + mi*16 + lr + h*8;
            int py = pp / W2 - 1, px = pp % W2 - 1;
            bool ok = (pp < PPn) && (unsigned)py < (unsigned)H && (unsigned)px < (unsigned)W;
            if (!ok) continue;
            float* ob = obase + py*W + px;
#pragma unroll
            for (int ni = 0; ni < 7; ni++) {
                int n = wn*56 + ni*8 + 2*kc;
                if (n < OMC)   ob[(size_t)n*HW]     = d[mi][ni][h*2+0] + bom[n];
                if (n+1 < OMC) ob[(size_t)(n+1)*HW] = d[mi][ni][h*2+1] + bom[n+1];
            }
        }
    }
}

// ---------------- DCNv4 bilinear gather (branchless corners) -----------------
__global__ __launch_bounds__(256) void k_dcn() {
    int bx = blockIdx.x;
    int s = (bx >= 512) + (bx >= 640);
    int base = SEL3(s, 0, 512, 640);
    int H = 64 >> s, W = 64 >> s, HW = H*W;
    int SOFF = SEL3(s, 0, 4096, 5120);
    int warp = threadIdx.x >> 5, lane = threadIdx.x & 31;
    int hw = (bx - base)*8 + warp;
    int g = blockIdx.y, b = blockIdx.z;
    int h = hw / W, w = hw % W;
    const float* omb = g_om + OMOFF(s) + (size_t)b*OMC*HW;
    const float* xb  = g_xt + ((size_t)b*TP + SOFF)*CC + g*64;
    ull acc = 0ull;
#pragma unroll
    for (int k = 0; k < 9; k++) {
        int ky = k/3 - 1, kx = k%3 - 1;
        int ch = (g*9 + k)*3;
        float offy = omb[(size_t)(ch+0)*HW + hw];
        float offx = omb[(size_t)(ch+1)*HW + hw];
        float msk  = omb[(size_t)(ch+2)*HW + hw];
        float py = (float)(h + ky) + offy;
        float px = (float)(w + kx) + offx;
        float y0f = floorf(py), x0f = floorf(px);
        float fy = py - y0f, fx = px - x0f;
        int y0 = (int)y0f, x0 = (int)x0f;
#pragma unroll
        for (int t = 0; t < 4; t++) {
            int dy = t >> 1, dx = t & 1;
            int yy = y0 + dy, xx = x0 + dx;
            float wgt = (dy ? fy : 1.f - fy) * (dx ? fx : 1.f - fx);
            bool valid = (yy >= 0) && (yy < H) && (xx >= 0) && (xx < W);
            float weff = valid ? wgt * msk : 0.f;
            int yc = min(max(yy, 0), H-1);
            int xc = min(max(xx, 0), W-1);
            const ull* p = (const ull*)(xb + (size_t)(yc*W + xc)*CC);
            f2fma(acc, f2pk(weff, weff), p[lane]);
        }
    }
    ((ull*)(g_dcn + ((size_t)b*TP + SOFF + hw)*CC + g*64))[lane] = acc;
}

// ---------------- 1x1 projection GEMM (f32x2); M = NB*TP = 10752 -------------
__global__ __launch_bounds__(256,2) void k_proj(const float* __restrict__ wp,
                                                const float* __restrict__ bp) {
    __shared__ float As[16][128];
    __shared__ ull   Bs2[16][64];
    int tid = threadIdx.x;
    int m0 = blockIdx.x*128, n0 = blockIdx.y*64;
    ull acc[4][4];
#pragma unroll
    for (int i = 0; i < 4; i++)
#pragma unroll
        for (int j = 0; j < 4; j++) acc[i][j] = 0ull;
    int lm = tid >> 1, lkq = (tid & 1)*8;
    int ln = tid >> 2, lk4 = (tid & 3)*4;
    int tm = tid >> 4, tn = tid & 15;
    for (int k0 = 0; k0 < CC; k0 += 16) {
        float4 aq0 = *(const float4*)(g_dcn + (size_t)(m0+lm)*CC + k0 + lkq);
        float4 aq1 = *(const float4*)(g_dcn + (size_t)(m0+lm)*CC + k0 + lkq + 4);
        float4 bv = *(const float4*)(wp    + (size_t)(n0+ln)*CC + k0 + lk4);
        __syncthreads();
        As[lkq+0][lm] = aq0.x; As[lkq+1][lm] = aq0.y; As[lkq+2][lm] = aq0.z; As[lkq+3][lm] = aq0.w;
        As[lkq+4][lm] = aq1.x; As[lkq+5][lm] = aq1.y; As[lkq+6][lm] = aq1.z; As[lkq+7][lm] = aq1.w;
        Bs2[lk4+0][ln] = f2pk(bv.x, bv.x);
        Bs2[lk4+1][ln] = f2pk(bv.y, bv.y);
        Bs2[lk4+2][ln] = f2pk(bv.z, bv.z);
        Bs2[lk4+3][ln] = f2pk(bv.w, bv.w);
        __syncthreads();
#pragma unroll
        for (int kk = 0; kk < 16; kk++) {
            ull ra[4], rb[4];
#pragma unroll
            for (int i = 0; i < 4; i++) ra[i] = *(const ull*)&As[kk][2*tm + 32*i];
#pragma unroll
            for (int j = 0; j < 4; j++) rb[j] = Bs2[kk][tn + 16*j];
#pragma unroll
            for (int i = 0; i < 4; i++)
#pragma unroll
                for (int j = 0; j < 4; j++) f2fma(acc[i][j], ra[i], rb[j]);
        }
    }
#pragma unroll
    for (int i = 0; i < 4; i++)
#pragma unroll
        for (int j = 0; j < 4; j++) {
            float2 v = f2up(acc[i][j]);
            int mm = m0 + 2*tm + 32*i, nn = n0 + tn + 16*j;
            float bia = bp[nn];
            g_d[(size_t)mm*CC + nn]     = v.x + bia;
            g_d[(size_t)(mm+1)*CC + nn] = v.y + bia;
        }
}

// ---------------- channel LayerNorm + sigmoid gate (warp per row) ------------
__global__ __launch_bounds__(256) void k_lngate(const float* __restrict__ lng,
                                                const float* __restrict__ lnb) {
    int warp = threadIdx.x >> 5, lane = threadIdx.x & 31;
    int r = blockIdx.x*8 + warp;
    size_t base = (size_t)r*CC;
    float4 v0 = *(const float4*)(g_d + base + lane*8);
    float4 v1 = *(const float4*)(g_d + base + lane*8 + 4);
    float s = v0.x+v0.y+v0.z+v0.w + v1.x+v1.y+v1.z+v1.w;
    float q = v0.x*v0.x+v0.y*v0.y+v0.z*v0.z+v0.w*v0.w
            + v1.x*v1.x+v1.y*v1.y+v1.z*v1.z+v1.w*v1.w;
#pragma unroll
    for (int o = 16; o; o >>= 1) {
        s += __shfl_xor_sync(0xffffffffu, s, o);
        q += __shfl_xor_sync(0xffffffffu, q, o);
    }
    float mu = s * (1.f/CC);
    float rs = rsqrtf(q * (1.f/CC) - mu*mu + 1e-5f);
    float4 g0 = *(const float4*)(lng + lane*8);
    float4 g1 = *(const float4*)(lng + lane*8 + 4);
    float4 b0 = *(const float4*)(lnb + lane*8);
    float4 b1 = *(const float4*)(lnb + lane*8 + 4);
    float4 x0 = *(const float4*)(g_xt + base + lane*8);
    float4 x1 = *(const float4*)(g_xt + base + lane*8 + 4);
    float4 o0, o1;
    o0.x = x0.x / (1.f + expf(-((v0.x-mu)*rs*g0.x + b0.x)));
    o0.y = x0.y / (1.f + expf(-((v0.y-mu)*rs*g0.y + b0.y)));
    o0.z = x0.z / (1.f + expf(-((v0.z-mu)*rs*g0.z + b0.z)));
    o0.w = x0.w / (1.f + expf(-((v0.w-mu)*rs*g0.w + b0.w)));
    o1.x = x1.x / (1.f + expf(-((v1.x-mu)*rs*g1.x + b1.x)));
    o1.y = x1.y / (1.f + expf(-((v1.y-mu)*rs*g1.y + b1.y)));
    o1.z = x1.z / (1.f + expf(-((v1.z-mu)*rs*g1.z + b1.z)));
    o1.w = x1.w / (1.f + expf(-((v1.w-mu)*rs*g1.w + b1.w)));
    *(float4*)(g_x2t + base + lane*8)     = o0;
    *(float4*)(g_x2t + base + lane*8 + 4) = o1;
}

// ---------------- task attention --------------------------------------------
__global__ __launch_bounds__(256) void k_pool2a() {
    int slab = blockIdx.x, b = blockIdx.y;
    int s = (slab >= 64) + (slab >= 80);
    int sbase = SEL3(s, 0, 64, 80);
    int SOFF = SEL3(s, 0, 4096, 5120);
    int c = threadIdx.x;
    int r0 = SOFF + (slab - sbase)*64;
    float v = 0.f;
    for (int r = r0; r < r0 + 64; r++)
        v += g_x2t[((size_t)b*TP + r)*CC + c];
    g_part[(b*84 + slab)*CC + c] = v;
}

__global__ __launch_bounds__(256) void k_pool2b() {
    int s = blockIdx.x, b = blockIdx.y, c = threadIdx.x;
    int slabs = SEL3(s, 64, 16, 4);
    int sbase = SEL3(s, 0, 64, 80);
    int HW = 4096 >> (2*s);
    float v = 0.f;
    for (int i = 0; i < slabs; i++) v += g_part[(b*84 + sbase + i)*CC + c];
    g_pool2[(s*NB + b)*CC + c] = v / (float)HW;
}

__global__ __launch_bounds__(256) void k_task_gemv(
        const float* __restrict__ wa1, const float* __restrict__ ba1,
        const float* __restrict__ wb1, const float* __restrict__ bb1,
        const float* __restrict__ wa2, const float* __restrict__ ba2,
        const float* __restrict__ wb2, const float* __restrict__ bb2) {
    int gw = (blockIdx.x*blockDim.x + threadIdx.x) >> 5;
    int lane = threadIdx.x & 31;
    if (gw >= 4*3*NB*CC) return;
    int which = gw / (3*NB*CC);
    int rem = gw % (3*NB*CC);
    int sb = rem / CC, o = rem % CC;
    const float* ws = (which == 0) ? wa1 : (which == 1) ? wb1 : (which == 2) ? wa2 : wb2;
    const float* bs = (which == 0) ? ba1 : (which == 1) ? bb1 : (which == 2) ? ba2 : bb2;
    const float* wr = ws + (size_t)o*CC;
    const float* pr = g_pool2 + sb*CC;
    float v = 0.f;
#pragma unroll
    for (int i = 0; i < CC/32; i++) v = fmaf(wr[lane + i*32], pr[lane + i*32], v);
#pragma unroll
    for (int o2 = 16; o2; o2 >>= 1) v += __shfl_down_sync(0xffffffffu, v, o2);
    if (!lane) g_ab[(which*3*NB + sb)*CC + o] = fmaxf(v + bs[o], 0.f);
}

__global__ __launch_bounds__(256) void k_taskout(float* __restrict__ out) {
    __shared__ float t[32][33];
    int bx = blockIdx.x;
    int s = (bx >= 128) + (bx >= 160);
    int base = SEL3(s, 0, 128, 160);
    int HW = 4096 >> (2*s);
    int SOFF = SEL3(s, 0, 4096, 5120);
    size_t OOFF = (size_t)NB*CC*SOFF;
    int b = blockIdx.z;
    int hw0 = (bx - base)*32, c0 = blockIdx.y*32;
    int tx = threadIdx.x, ty = threadIdx.y;
    int sb = s*NB + b;
#pragma unroll
    for (int i = 0; i < 4; i++) {
        int hw = hw0 + ty + i*8, c = c0 + tx;
        float v  = g_x2t[((size_t)b*TP + SOFF + hw)*CC + c];
        float A1 = g_ab[(0*3*NB + sb)*CC + c];
        float B1 = g_ab[(1*3*NB + sb)*CC + c];
        float A2 = g_ab[(2*3*NB + sb)*CC + c];
        float B2 = g_ab[(3*3*NB + sb)*CC + c];
        t[tx][ty + i*8] = fmaxf(fmaf(A1, v, B1), fmaf(A2, v, B2));
    }
    __syncthreads();
#pragma unroll
    for (int i = 0; i < 4; i++) {
        int c = c0 + ty + i*8, hw = hw0 + tx;
        out[OOFF + ((size_t)b*CC + c)*HW + hw] = t[ty + i*8][tx];
    }
}

// ---------------- launch ------------------------------------------------------
extern "C" void kernel_launch(void* const* d_in, const int* in_sizes, int n_in,
                              void* d_out, int out_size) {
    const float* f1 = (const float*)d_in[0];
    const float* f2 = (const float*)d_in[1];
    const float* f3 = (const float*)d_in[2];
    const float* w_scale = (const float*)d_in[3];
    const float* b_scale = (const float*)d_in[4];
    const float* w_om    = (const float*)d_in[5];
    const float* b_om    = (const float*)d_in[6];
    const float* w_proj  = (const float*)d_in[7];
    const float* b_proj  = (const float*)d_in[8];
    const float* ln_g    = (const float*)d_in[9];
    const float* ln_b    = (const float*)d_in[10];
    const float* wa1 = (const float*)d_in[11];
    const float* ba1 = (const float*)d_in[12];
    const float* wb1 = (const float*)d_in[13];
    const float* bb1 = (const float*)d_in[14];
    const float* wa2 = (const float*)d_in[15];
    const float* ba2 = (const float*)d_in[16];
    const float* wb2 = (const float*)d_in[17];
    const float* bb2 = (const float*)d_in[18];
    float* out = (float*)d_out;

    k_wprep2<<<(72*3584 + 255)/256, 256>>>(w_om);
    k_pool<<<dim3(CC, NB, 3), 256>>>(f1, f2, f3);
    k_scale_gemv<<<(3*NB*CC*32 + 255)/256, 256>>>(w_scale, b_scale);
    k_apply<<<dim3(168, CC/32, NB), dim3(32, 8)>>>(f1, f2, f3);
    k_convmma<<<96, 256>>>(b_om);
    k_dcn<<<dim3(672, GG, NB), 256>>>();
    k_proj<<<dim3(NB*TP/128, CC/64), 256>>>(w_proj, b_proj);
    k_lngate<<<NB*TP/8, 256>>>(ln_g, ln_b);
    k_pool2a<<<dim3(84, NB), 256>>>();
    k_pool2b<<<dim3(3, NB), 256>>>();
    k_task_gemv<<<(4*3*NB*CC*32 + 255)/256, 256>>>(wa1, ba1, wb1, bb1, wa2, ba2, wb2, bb2);
    k_taskout<<<dim3(168, CC/32, NB), dim3(32, 8)>>>(out);
}

// round 9
// speedup vs baseline: 6.7028x; 1.2307x over previous
#include <cuda_runtime.h>
#include <math.h>
#include <stdint.h>

#define CC    256
#define GG    4
#define NB    2
#define OMC   108          // G*K*3
#define TP    5376         // total pixels per batch across scales (4096+1024+256)
#define SEL3(s,a,b,c) ((s)==0 ? (a) : ((s)==1 ? (b) : (c)))

typedef unsigned long long ull;

__device__ __forceinline__ ull f2pk(float lo, float hi) {
    ull r; asm("mov.b64 %0, {%1, %2};" : "=l"(r) : "f"(lo), "f"(hi)); return r;
}
__device__ __forceinline__ void f2fma(ull &d, ull a, ull b) {
    asm("fma.rn.f32x2 %0, %1, %2, %0;" : "+l"(d) : "l"(a), "l"(b));
}
__device__ __forceinline__ float2 f2up(ull v) {
    float2 o; asm("mov.b64 {%0, %1}, %2;" : "=f"(o.x), "=f"(o.y) : "l"(v)); return o;
}
__device__ __forceinline__ float tf32r(float x) {
    float r; asm("cvt.rna.tf32.f32 %0, %1;" : "=f"(r) : "f"(x)); return r;
}

// warp-level tf32 MMA (sm_80+ path; compiles on plain sm_103)
#define MMA8(d, a, b0, b1) \
    asm volatile("mma.sync.aligned.m16n8k8.row.col.f32.tf32.tf32.f32 " \
        "{%0,%1,%2,%3}, {%4,%5,%6,%7}, {%8,%9}, {%0,%1,%2,%3};" \
        : "+f"((d)[0]), "+f"((d)[1]), "+f"((d)[2]), "+f"((d)[3]) \
        : "r"((a)[0]), "r"((a)[1]), "r"((a)[2]), "r"((a)[3]), "r"(b0), "r"(b1))

// ---------------- scratch (static device globals) ---------------------------
__device__ float g_xt [NB*TP*CC];        // scaled input, pixel-major [b][p][c]
__device__ float g_om [NB*OMC*TP];       // offset/mask conv output (per-scale blocks)
__device__ float g_dcn[NB*TP*CC];
__device__ float g_d  [NB*TP*CC];
__device__ float g_x2t[NB*TP*CC];
__device__ float g_wt [72*32*112];       // conv weights tf32: [tap*8+ck][kk(32)][n(112)]
__device__ float g_wpj[CC*CC];           // proj weights tf32, transposed: [k][n]
__device__ float g_pool [3*NB*CC];
__device__ float g_sfac [3*NB*CC];
__device__ float g_part [NB*84*CC];
__device__ float g_pool2[3*NB*CC];
__device__ float g_ab  [4*3*NB*CC];

#define OMOFF(s) SEL3(s, 0, 884736, 1105920)

// ---------------- weight prep: conv tiles + proj transpose (merged) ----------
__global__ __launch_bounds__(256) void k_wprep2(const float* __restrict__ wom,
                                                const float* __restrict__ wp) {
    int bx = blockIdx.x;
    if (bx < 1008) {
        int idx = bx*256 + threadIdx.x;
        int i = idx / 3584, r = idx % 3584, kk = r / 112, n = r % 112;
        int t = i >> 3, ck = i & 7, c = ck*32 + kk;
        float v = (n < OMC) ? wom[n*2304 + c*9 + t] : 0.f;
        g_wt[idx] = tf32r(v);
    } else {
        int idx = (bx - 1008)*256 + threadIdx.x;   // < 65536
        int k = idx >> 8, n = idx & 255;
        g_wpj[idx] = tf32r(wp[n*CC + k]);
    }
}

// ---------------- stage A: channel scale attention ---------------------------
__global__ __launch_bounds__(256) void k_pool(const float* __restrict__ f1,
                                              const float* __restrict__ f2,
                                              const float* __restrict__ f3) {
    int c = blockIdx.x, b = blockIdx.y, s = blockIdx.z;
    int HW = 4096 >> (2*s);
    const float* x = SEL3(s, f1, f2, f3);
    const float* p = x + ((size_t)b*CC + c)*HW;
    float v = 0.f;
    for (int i = threadIdx.x; i < HW; i += 256) v += p[i];
    __shared__ float sm[8];
    int lane = threadIdx.x & 31, wid = threadIdx.x >> 5;
#pragma unroll
    for (int o = 16; o; o >>= 1) v += __shfl_down_sync(0xffffffffu, v, o);
    if (!lane) sm[wid] = v;
    __syncthreads();
    if (threadIdx.x == 0) {
        float t = 0.f;
#pragma unroll
        for (int i = 0; i < 8; i++) t += sm[i];
        g_pool[(s*NB + b)*CC + c] = t / (float)HW;
    }
}

__global__ __launch_bounds__(256) void k_scale_gemv(const float* __restrict__ wsc,
                                                    const float* __restrict__ bsc) {
    int gw = (blockIdx.x*blockDim.x + threadIdx.x) >> 5;
    int lane = threadIdx.x & 31;
    if (gw >= 3*NB*CC) return;
    int sb = gw / CC, o = gw % CC;
    const float* wr = wsc + (size_t)o*CC;
    const float* pr = g_pool + sb*CC;
    float v = 0.f;
#pragma unroll
    for (int i = 0; i < CC/32; i++) v = fmaf(wr[lane + i*32], pr[lane + i*32], v);
#pragma unroll
    for (int o2 = 16; o2; o2 >>= 1) v += __shfl_down_sync(0xffffffffu, v, o2);
    if (!lane) {
        v = (v + bsc[o] + 1.f) * 0.5f;
        g_sfac[sb*CC + o] = fminf(fmaxf(v, 0.f), 1.f);
    }
}

__global__ __launch_bounds__(256) void k_apply(const float* __restrict__ f1,
                                               const float* __restrict__ f2,
                                               const float* __restrict__ f3) {
    __shared__ float t[32][33];
    int bx = blockIdx.x;
    int s = (bx >= 128) + (bx >= 160);
    int base = SEL3(s, 0, 128, 160);
    int HW = 4096 >> (2*s);
    int SOFF = SEL3(s, 0, 4096, 5120);
    const float* x = SEL3(s, f1, f2, f3);
    int b = blockIdx.z;
    int hw0 = (bx - base)*32, c0 = blockIdx.y*32;
    int tx = threadIdx.x, ty = threadIdx.y;
#pragma unroll
    for (int i = 0; i < 4; i++) {
        int c = c0 + ty + i*8;
        t[ty + i*8][tx] = x[((size_t)b*CC + c)*HW + hw0 + tx] * g_sfac[(s*NB + b)*CC + c];
    }
    __syncthreads();
#pragma unroll
    for (int i = 0; i < 4; i++) {
        int hw = hw0 + ty + i*8;
        g_xt[((size_t)b*TP + SOFF + hw)*CC + c0 + tx] = t[tx][ty + i*8];
    }
}

// ---------------- 3x3 conv via mma.sync tf32 implicit GEMM -------------------
__global__ __launch_bounds__(256) void k_convmma(const float* __restrict__ bom) {
    __shared__ float As[128*36];
    __shared__ float Bs[32*120];

    int tid = threadIdx.x, wid = tid >> 5, lane = tid & 31;
    int x = blockIdx.x;
    int s = (x >= 70) + (x >= 90);
    int r = x - SEL3(s, 0, 70, 90);
    int TILES = SEL3(s, 35, 10, 3);
    int b = r / TILES, tile = r % TILES;
    int H = 64 >> s, W = H, HW = H*W, W2 = W + 2, PPn = (H+2)*(W+2);
    int SOFF = SEL3(s, 0, 4096, 5120);
    int p0 = tile*128;
    const float* xb = g_xt + ((size_t)b*TP + SOFF)*CC;

    int q = tid & 7;
    int pyb[4], pxb[4], rowk[4];
    bool ppok[4];
    int bkk[4], bnq[4];
    bool bok[4];
#pragma unroll
    for (int k = 0; k < 4; k++) {
        rowk[k] = (tid >> 3) + 32*k;
        int pp = p0 + rowk[k];
        ppok[k] = pp < PPn;
        pyb[k] = pp / W2 - 1;
        pxb[k] = pp % W2 - 1;
        int u = tid + 256*k;
        bok[k] = u < 896;
        bkk[k] = u / 28;
        bnq[k] = u % 28;
    }

    float4 rA[4], rB[4];
#define LOADI(i) do {                                                            \
    int _t = (i) >> 3, _ck = (i) & 7;                                            \
    int _dy = _t/3 - 1, _dx = _t%3 - 1;                                          \
    _Pragma("unroll")                                                            \
    for (int k = 0; k < 4; k++) {                                                \
        int _py = pyb[k] + _dy, _px = pxb[k] + _dx;                              \
        bool _v = ppok[k] && (unsigned)_py < (unsigned)H && (unsigned)_px < (unsigned)W; \
        float4 _val = make_float4(0.f, 0.f, 0.f, 0.f);                           \
        if (_v) _val = *(const float4*)(xb + (size_t)(_py*W + _px)*CC + _ck*32 + q*4); \
        rA[k] = _val;                                                            \
        float4 _bv = make_float4(0.f, 0.f, 0.f, 0.f);                            \
        if (bok[k]) _bv = *(const float4*)(g_wt + (size_t)(i)*3584 + bkk[k]*112 + bnq[k]*4); \
        rB[k] = _bv;                                                             \
    }                                                                            \
} while (0)

    float d[2][7][4];
#pragma unroll
    for (int mi = 0; mi < 2; mi++)
#pragma unroll
        for (int ni = 0; ni < 7; ni++)
#pragma unroll
            for (int e = 0; e < 4; e++) d[mi][ni][e] = 0.f;

    int wm = wid & 3, wn = wid >> 2;
    int lr = lane >> 2, kc = lane & 3;
    const uint32_t* A32 = (const uint32_t*)As;
    const uint32_t* B32 = (const uint32_t*)Bs;

    LOADI(0);
    for (int i = 0; i < 72; i++) {
        if (i > 0) __syncthreads();
#pragma unroll
        for (int k = 0; k < 4; k++) {
            float4 v = rA[k];
            v.x = tf32r(v.x); v.y = tf32r(v.y); v.z = tf32r(v.z); v.w = tf32r(v.w);
            *(float4*)(As + rowk[k]*36 + q*4) = v;
            if (bok[k]) *(float4*)(Bs + bkk[k]*120 + bnq[k]*4) = rB[k];
        }
        if (i + 1 < 72) LOADI(i + 1);
        __syncthreads();

#pragma unroll
        for (int kq = 0; kq < 32; kq += 8) {
            uint32_t a[2][4];
#pragma unroll
            for (int mi = 0; mi < 2; mi++) {
                int rr = wm*32 + mi*16 + lr;
                a[mi][0] = A32[rr*36 + kq + kc];
                a[mi][1] = A32[(rr+8)*36 + kq + kc];
                a[mi][2] = A32[rr*36 + kq + kc + 4];
                a[mi][3] = A32[(rr+8)*36 + kq + kc + 4];
            }
#pragma unroll
            for (int ni = 0; ni < 7; ni++) {
                int nn = wn*56 + ni*8 + lr;
                uint32_t b0 = B32[(kq+kc)*120 + nn];
                uint32_t b1 = B32[(kq+kc+4)*120 + nn];
                MMA8(d[0][ni], a[0], b0, b1);
                MMA8(d[1][ni], a[1], b0, b1);
            }
        }
    }

    float* obase = g_om + OMOFF(s) + (size_t)b*OMC*HW;
#pragma unroll
    for (int mi = 0; mi < 2; mi++) {
#pragma unroll
        for (int h = 0; h < 2; h++) {
            int pp = p0 + wm*32 + mi*16 + lr + h*8;
            int py = pp / W2 - 1, px = pp % W2 - 1;
            bool ok = (pp < PPn) && (unsigned)py < (unsigned)H && (unsigned)px < (unsigned)W;
            if (!ok) continue;
            float* ob = obase + py*W + px;
#pragma unroll
            for (int ni = 0; ni < 7; ni++) {
                int n = wn*56 + ni*8 + 2*kc;
                if (n < OMC)   ob[(size_t)n*HW]     = d[mi][ni][h*2+0] + bom[n];
                if (n+1 < OMC) ob[(size_t)(n+1)*HW] = d[mi][ni][h*2+1] + bom[n+1];
            }
        }
    }
}

// ---------------- DCNv4 bilinear gather (branchless corners) -----------------
__global__ __launch_bounds__(256) void k_dcn() {
    int bx = blockIdx.x;
    int s = (bx >= 512) + (bx >= 640);
    int base = SEL3(s, 0, 512, 640);
    int H = 64 >> s, W = 64 >> s, HW = H*W;
    int SOFF = SEL3(s, 0, 4096, 5120);
    int warp = threadIdx.x >> 5, lane = threadIdx.x & 31;
    int hw = (bx - base)*8 + warp;
    int g = blockIdx.y, b = blockIdx.z;
    int h = hw / W, w = hw % W;
    const float* omb = g_om + OMOFF(s) + (size_t)b*OMC*HW;
    const float* xb  = g_xt + ((size_t)b*TP + SOFF)*CC + g*64;
    ull acc = 0ull;
#pragma unroll
    for (int k = 0; k < 9; k++) {
        int ky = k/3 - 1, kx = k%3 - 1;
        int ch = (g*9 + k)*3;
        float offy = omb[(size_t)(ch+0)*HW + hw];
        float offx = omb[(size_t)(ch+1)*HW + hw];
        float msk  = omb[(size_t)(ch+2)*HW + hw];
        float py = (float)(h + ky) + offy;
        float px = (float)(w + kx) + offx;
        float y0f = floorf(py), x0f = floorf(px);
        float fy = py - y0f, fx = px - x0f;
        int y0 = (int)y0f, x0 = (int)x0f;
#pragma unroll
        for (int t = 0; t < 4; t++) {
            int dy = t >> 1, dx = t & 1;
            int yy = y0 + dy, xx = x0 + dx;
            float wgt = (dy ? fy : 1.f - fy) * (dx ? fx : 1.f - fx);
            bool valid = (yy >= 0) && (yy < H) && (xx >= 0) && (xx < W);
            float weff = valid ? wgt * msk : 0.f;
            int yc = min(max(yy, 0), H-1);
            int xc = min(max(xx, 0), W-1);
            const ull* p = (const ull*)(xb + (size_t)(yc*W + xc)*CC);
            f2fma(acc, f2pk(weff, weff), p[lane]);
        }
    }
    ((ull*)(g_dcn + ((size_t)b*TP + SOFF + hw)*CC + g*64))[lane] = acc;
}

// ---------------- 1x1 projection via mma.sync tf32 ---------------------------
// grid (84, 2): 128m x 128n per CTA, K=256 in 8 iters of 32
__global__ __launch_bounds__(256) void k_projmma(const float* __restrict__ bp) {
    __shared__ float As[128*36];
    __shared__ float Bs[32*152];     // 152 mod 32 = 24 -> conflict-free b-frags

    int tid = threadIdx.x, wid = tid >> 5, lane = tid & 31;
    int m0 = blockIdx.x*128, n0 = blockIdx.y*128;

    int q = tid & 7;
    int rowk[4], bkk[4], bnq[4];
#pragma unroll
    for (int k = 0; k < 4; k++) {
        rowk[k] = (tid >> 3) + 32*k;
        int u = tid + 256*k;           // < 1024
        bkk[k] = u >> 5;
        bnq[k] = u & 31;
    }

    float4 rA[4], rB[4];
#define PLOADI(i) do {                                                           \
    int _k0 = (i)*32;                                                            \
    _Pragma("unroll")                                                            \
    for (int k = 0; k < 4; k++) {                                                \
        rA[k] = *(const float4*)(g_dcn + (size_t)(m0 + rowk[k])*CC + _k0 + q*4); \
        rB[k] = *(const float4*)(g_wpj + (size_t)(_k0 + bkk[k])*CC + n0 + bnq[k]*4); \
    }                                                                            \
} while (0)

    float d[2][8][4];
#pragma unroll
    for (int mi = 0; mi < 2; mi++)
#pragma unroll
        for (int ni = 0; ni < 8; ni++)
#pragma unroll
            for (int e = 0; e < 4; e++) d[mi][ni][e] = 0.f;

    int wm = wid & 3, wn = wid >> 2;
    int lr = lane >> 2, kc = lane & 3;
    const uint32_t* A32 = (const uint32_t*)As;
    const uint32_t* B32 = (const uint32_t*)Bs;

    PLOADI(0);
    for (int i = 0; i < 8; i++) {
        if (i > 0) __syncthreads();
#pragma unroll
        for (int k = 0; k < 4; k++) {
            float4 v = rA[k];
            v.x = tf32r(v.x); v.y = tf32r(v.y); v.z = tf32r(v.z); v.w = tf32r(v.w);
            *(float4*)(As + rowk[k]*36 + q*4) = v;
            *(float4*)(Bs + bkk[k]*152 + bnq[k]*4) = rB[k];
        }
        if (i + 1 < 8) PLOADI(i + 1);
        __syncthreads();

#pragma unroll
        for (int kq = 0; kq < 32; kq += 8) {
            uint32_t a[2][4];
#pragma unroll
            for (int mi = 0; mi < 2; mi++) {
                int rr = wm*32 + mi*16 + lr;
                a[mi][0] = A32[rr*36 + kq + kc];
                a[mi][1] = A32[(rr+8)*36 + kq + kc];
                a[mi][2] = A32[rr*36 + kq + kc + 4];
                a[mi][3] = A32[(rr+8)*36 + kq + kc + 4];
            }
#pragma unroll
            for (int ni = 0; ni < 8; ni++) {
                int nn = wn*64 + ni*8 + lr;
                uint32_t b0 = B32[(kq+kc)*152 + nn];
                uint32_t b1 = B32[(kq+kc+4)*152 + nn];
                MMA8(d[0][ni], a[0], b0, b1);
                MMA8(d[1][ni], a[1], b0, b1);
            }
        }
    }

    // epilogue: M, N exact multiples -> no bounds checks
#pragma unroll
    for (int mi = 0; mi < 2; mi++) {
#pragma unroll
        for (int h = 0; h < 2; h++) {
            int m = m0 + wm*32 + mi*16 + lr + h*8;
            float* orow = g_d + (size_t)m*CC;
#pragma unroll
            for (int ni = 0; ni < 8; ni++) {
                int n = n0 + wn*64 + ni*8 + 2*kc;
                float2 v = make_float2(d[mi][ni][h*2+0] + bp[n],
                                       d[mi][ni][h*2+1] + bp[n+1]);
                *(float2*)(orow + n) = v;
            }
        }
    }
}

// ---------------- channel LayerNorm + sigmoid gate (warp per row) ------------
__global__ __launch_bounds__(256) void k_lngate(const float* __restrict__ lng,
                                                const float* __restrict__ lnb) {
    int warp = threadIdx.x >> 5, lane = threadIdx.x & 31;
    int r = blockIdx.x*8 + warp;
    size_t base = (size_t)r*CC;
    float4 v0 = *(const float4*)(g_d + base + lane*8);
    float4 v1 = *(const float4*)(g_d + base + lane*8 + 4);
    float s = v0.x+v0.y+v0.z+v0.w + v1.x+v1.y+v1.z+v1.w;
    float q = v0.x*v0.x+v0.y*v0.y+v0.z*v0.z+v0.w*v0.w
            + v1.x*v1.x+v1.y*v1.y+v1.z*v1.z+v1.w*v1.w;
#pragma unroll
    for (int o = 16; o; o >>= 1) {
        s += __shfl_xor_sync(0xffffffffu, s, o);
        q += __shfl_xor_sync(0xffffffffu, q, o);
    }
    float mu = s * (1.f/CC);
    float rs = rsqrtf(q * (1.f/CC) - mu*mu + 1e-5f);
    float4 g0 = *(const float4*)(lng + lane*8);
    float4 g1 = *(const float4*)(lng + lane*8 + 4);
    float4 b0 = *(const float4*)(lnb + lane*8);
    float4 b1 = *(const float4*)(lnb + lane*8 + 4);
    float4 x0 = *(const float4*)(g_xt + base + lane*8);
    float4 x1 = *(const float4*)(g_xt + base + lane*8 + 4);
    float4 o0, o1;
    o0.x = x0.x / (1.f + expf(-((v0.x-mu)*rs*g0.x + b0.x)));
    o0.y = x0.y / (1.f + expf(-((v0.y-mu)*rs*g0.y + b0.y)));
    o0.z = x0.z / (1.f + expf(-((v0.z-mu)*rs*g0.z + b0.z)));
    o0.w = x0.w / (1.f + expf(-((v0.w-mu)*rs*g0.w + b0.w)));
    o1.x = x1.x / (1.f + expf(-((v1.x-mu)*rs*g1.x + b1.x)));
    o1.y = x1.y / (1.f + expf(-((v1.y-mu)*rs*g1.y + b1.y)));
    o1.z = x1.z / (1.f + expf(-((v1.z-mu)*rs*g1.z + b1.z)));
    o1.w = x1.w / (1.f + expf(-((v1.w-mu)*rs*g1.w + b1.w)));
    *(float4*)(g_x2t + base + lane*8)     = o0;
    *(float4*)(g_x2t + base + lane*8 + 4) = o1;
}

// ---------------- task attention --------------------------------------------
__global__ __launch_bounds__(256) void k_pool2a() {
    int slab = blockIdx.x, b = blockIdx.y;
    int s = (slab >= 64) + (slab >= 80);
    int sbase = SEL3(s, 0, 64, 80);
    int SOFF = SEL3(s, 0, 4096, 5120);
    int c = threadIdx.x;
    int r0 = SOFF + (slab - sbase)*64;
    float v = 0.f;
    for (int r = r0; r < r0 + 64; r++)
        v += g_x2t[((size_t)b*TP + r)*CC + c];
    g_part[(b*84 + slab)*CC + c] = v;
}

__global__ __launch_bounds__(256) void k_pool2b() {
    int s = blockIdx.x, b = blockIdx.y, c = threadIdx.x;
    int slabs = SEL3(s, 64, 16, 4);
    int sbase = SEL3(s, 0, 64, 80);
    int HW = 4096 >> (2*s);
    float v = 0.f;
    for (int i = 0; i < slabs; i++) v += g_part[(b*84 + sbase + i)*CC + c];
    g_pool2[(s*NB + b)*CC + c] = v / (float)HW;
}

__global__ __launch_bounds__(256) void k_task_gemv(
        const float* __restrict__ wa1, const float* __restrict__ ba1,
        const float* __restrict__ wb1, const float* __restrict__ bb1,
        const float* __restrict__ wa2, const float* __restrict__ ba2,
        const float* __restrict__ wb2, const float* __restrict__ bb2) {
    int gw = (blockIdx.x*blockDim.x + threadIdx.x) >> 5;
    int lane = threadIdx.x & 31;
    if (gw >= 4*3*NB*CC) return;
    int which = gw / (3*NB*CC);
    int rem = gw % (3*NB*CC);
    int sb = rem / CC, o = rem % CC;
    const float* ws = (which == 0) ? wa1 : (which == 1) ? wb1 : (which == 2) ? wa2 : wb2;
    const float* bs = (which == 0) ? ba1 : (which == 1) ? bb1 : (which == 2) ? ba2 : bb2;
    const float* wr = ws + (size_t)o*CC;
    const float* pr = g_pool2 + sb*CC;
    float v = 0.f;
#pragma unroll
    for (int i = 0; i < CC/32; i++) v = fmaf(wr[lane + i*32], pr[lane + i*32], v);
#pragma unroll
    for (int o2 = 16; o2; o2 >>= 1) v += __shfl_down_sync(0xffffffffu, v, o2);
    if (!lane) g_ab[(which*3*NB + sb)*CC + o] = fmaxf(v + bs[o], 0.f);
}

__global__ __launch_bounds__(256) void k_taskout(float* __restrict__ out) {
    __shared__ float t[32][33];
    int bx = blockIdx.x;
    int s = (bx >= 128) + (bx >= 160);
    int base = SEL3(s, 0, 128, 160);
    int HW = 4096 >> (2*s);
    int SOFF = SEL3(s, 0, 4096, 5120);
    size_t OOFF = (size_t)NB*CC*SOFF;
    int b = blockIdx.z;
    int hw0 = (bx - base)*32, c0 = blockIdx.y*32;
    int tx = threadIdx.x, ty = threadIdx.y;
    int sb = s*NB + b;
#pragma unroll
    for (int i = 0; i < 4; i++) {
        int hw = hw0 + ty + i*8, c = c0 + tx;
        float v  = g_x2t[((size_t)b*TP + SOFF + hw)*CC + c];
        float A1 = g_ab[(0*3*NB + sb)*CC + c];
        float B1 = g_ab[(1*3*NB + sb)*CC + c];
        float A2 = g_ab[(2*3*NB + sb)*CC + c];
        float B2 = g_ab[(3*3*NB + sb)*CC + c];
        t[tx][ty + i*8] = fmaxf(fmaf(A1, v, B1), fmaf(A2, v, B2));
    }
    __syncthreads();
#pragma unroll
    for (int i = 0; i < 4; i++) {
        int c = c0 + ty + i*8, hw = hw0 + tx;
        out[OOFF + ((size_t)b*CC + c)*HW + hw] = t[ty + i*8][tx];
    }
}

// ---------------- launch ------------------------------------------------------
extern "C" void kernel_launch(void* const* d_in, const int* in_sizes, int n_in,
                              void* d_out, int out_size) {
    const float* f1 = (const float*)d_in[0];
    const float* f2 = (const float*)d_in[1];
    const float* f3 = (const float*)d_in[2];
    const float* w_scale = (const float*)d_in[3];
    const float* b_scale = (const float*)d_in[4];
    const float* w_om    = (const float*)d_in[5];
    const float* b_om    = (const float*)d_in[6];
    const float* w_proj  = (const float*)d_in[7];
    const float* b_proj  = (const float*)d_in[8];
    const float* ln_g    = (const float*)d_in[9];
    const float* ln_b    = (const float*)d_in[10];
    const float* wa1 = (const float*)d_in[11];
    const float* ba1 = (const float*)d_in[12];
    const float* wb1 = (const float*)d_in[13];
    const float* bb1 = (const float*)d_in[14];
    const float* wa2 = (const float*)d_in[15];
    const float* ba2 = (const float*)d_in[16];
    const float* wb2 = (const float*)d_in[17];
    const float* bb2 = (const float*)d_in[18];
    float* out = (float*)d_out;

    k_wprep2<<<1264, 256>>>(w_om, w_proj);
    k_pool<<<dim3(CC, NB, 3), 256>>>(f1, f2, f3);
    k_scale_gemv<<<(3*NB*CC*32 + 255)/256, 256>>>(w_scale, b_scale);
    k_apply<<<dim3(168, CC/32, NB), dim3(32, 8)>>>(f1, f2, f3);
    k_convmma<<<96, 256>>>(b_om);
    k_dcn<<<dim3(672, GG, NB), 256>>>();
    k_projmma<<<dim3(84, 2), 256>>>(b_proj);
    k_lngate<<<NB*TP/8, 256>>>(ln_g, ln_b);
    k_pool2a<<<dim3(84, NB), 256>>>();
    k_pool2b<<<dim3(3, NB), 256>>>();
    k_task_gemv<<<(4*3*NB*CC*32 + 255)/256, 256>>>(wa1, ba1, wb1, bb1, wa2, ba2, wb2, bb2);
    k_taskout<<<dim3(168, CC/32, NB), dim3(32, 8)>>>(out);
}